// round 5
// baseline (speedup 1.0000x reference)
#include <cuda_runtime.h>

// Problem constants
#define NN   100000   // batch rows
#define D_IN 500      // input features
#define HF   256      // hidden
#define MM   50000    // cluster rows
#define KC   40       // clusters
#define O2   1024     // OUT*OUT
#define EPSV 1e-5f

static inline int cdiv_h(int a, int b) { return (a + b - 1) / b; }

// ---------------- device scratch (static: no allocation in kernel_launch) ----
__device__ float g_H1[(size_t)NN * HF];     // x@W1^T + b1 (raw, pre-BN)
__device__ float g_H2[(size_t)NN * HF];     // h1'@W2^T + b2 (raw, pre-BN)
__device__ float g_XC[(size_t)MM * HF];     // gathered + BN2 + relu rows
__device__ float g_sum1[HF], g_sq1[HF], g_a1[HF], g_c1[HF];
__device__ float g_sum2[HF], g_sq2[HF], g_a2[HF], g_c2[HF];
__device__ float g_CFsum[KC * HF];
__device__ int   g_counts[KC];
__device__ int   g_labels[MM];
__device__ float g_PA[KC * O2];             // CF @ WfcA^T + bfc
__device__ float g_PB[KC * O2];             // CF @ WfcB^T + bfc

// ---------------- zero accumulators ----------------------------------------
__global__ void k_zero(float* s1, float* q1, float* s2, float* q2,
                       float* cfs, int* cnt) {
    int t = blockIdx.x * blockDim.x + threadIdx.x;
    if (t < HF) { s1[t] = 0.f; q1[t] = 0.f; s2[t] = 0.f; q2[t] = 0.f; }
    if (t < KC) cnt[t] = 0;
    if (t < KC * HF) cfs[t] = 0.f;
}

// ---------------- SGEMM: C[M,N] = opA(A[M,K]) @ B[N,K]^T + bias -------------
// 128x128 tile, BK=8, 8x8 per-thread microtile, 256 threads.
// AFF: apply h' = relu(aff_a[k]*h + aff_c[k]) to A elements (K must be <=256
// and a multiple of 8 in that mode; true for layer 2, K=256).
template <bool AFF>
__global__ void __launch_bounds__(256, 2)
k_gemm_tn(const float* __restrict__ A, const float* __restrict__ B,
          const float* __restrict__ bias, float* __restrict__ C,
          int Mrows, int Ncols, int K,
          const float* __restrict__ aff_a, const float* __restrict__ aff_c) {
    __shared__ float As[8][128];
    __shared__ float Bs[8][128];
    __shared__ float sAa[256], sAc[256];

    const int tx = threadIdx.x;
    if (AFF) {
        if (tx < K) { sAa[tx] = aff_a[tx]; sAc[tx] = aff_c[tx]; }
        // RACE FIX: the first mainloop iteration reads sAa[0..7]/sAc[0..7]
        // from other warps' writes; without this barrier warps 1..7 can read
        // stale SMEM (this was the rel_err=2e-2 bug). AFF is a compile-time
        // constant, so this barrier is uniformly reached by all threads.
        __syncthreads();
    }

    const int rowBase = blockIdx.y * 128;
    const int colBase = blockIdx.x * 128;
    const int lr = tx >> 1;            // 0..127
    const int lc = (tx & 1) * 4;       // 0 or 4
    const int tm = (tx >> 4) * 8;
    const int tn = (tx & 15) * 8;

    float acc[8][8];
#pragma unroll
    for (int i = 0; i < 8; i++)
#pragma unroll
        for (int j = 0; j < 8; j++) acc[i][j] = 0.f;

    const int aRow = rowBase + lr;
    const int bRow = colBase + lr;
    const float* Aptr = A + (size_t)aRow * K;
    const float* Bptr = B + (size_t)bRow * K;

    for (int k0 = 0; k0 < K; k0 += 8) {
        const int gk = k0 + lc;
        float4 av = make_float4(0.f, 0.f, 0.f, 0.f);
        if (aRow < Mrows) {
            if (gk + 3 < K) {
                av = *(const float4*)(Aptr + gk);
            } else {
                float t0 = (gk + 0 < K) ? Aptr[gk + 0] : 0.f;
                float t1 = (gk + 1 < K) ? Aptr[gk + 1] : 0.f;
                float t2 = (gk + 2 < K) ? Aptr[gk + 2] : 0.f;
                float t3 = (gk + 3 < K) ? Aptr[gk + 3] : 0.f;
                av = make_float4(t0, t1, t2, t3);
            }
        }
        if (AFF) {  // K multiple of 8 in this mode -> gk+3 < K always
            av.x = fmaxf(fmaf(sAa[gk + 0], av.x, sAc[gk + 0]), 0.f);
            av.y = fmaxf(fmaf(sAa[gk + 1], av.y, sAc[gk + 1]), 0.f);
            av.z = fmaxf(fmaf(sAa[gk + 2], av.z, sAc[gk + 2]), 0.f);
            av.w = fmaxf(fmaf(sAa[gk + 3], av.w, sAc[gk + 3]), 0.f);
        }
        float4 bv = make_float4(0.f, 0.f, 0.f, 0.f);
        if (bRow < Ncols) {
            if (gk + 3 < K) {
                bv = *(const float4*)(Bptr + gk);
            } else {
                float t0 = (gk + 0 < K) ? Bptr[gk + 0] : 0.f;
                float t1 = (gk + 1 < K) ? Bptr[gk + 1] : 0.f;
                float t2 = (gk + 2 < K) ? Bptr[gk + 2] : 0.f;
                float t3 = (gk + 3 < K) ? Bptr[gk + 3] : 0.f;
                bv = make_float4(t0, t1, t2, t3);
            }
        }
        __syncthreads();
        As[lc + 0][lr] = av.x; As[lc + 1][lr] = av.y;
        As[lc + 2][lr] = av.z; As[lc + 3][lr] = av.w;
        Bs[lc + 0][lr] = bv.x; Bs[lc + 1][lr] = bv.y;
        Bs[lc + 2][lr] = bv.z; Bs[lc + 3][lr] = bv.w;
        __syncthreads();
#pragma unroll
        for (int kk = 0; kk < 8; kk++) {
            float ra[8], rb[8];
#pragma unroll
            for (int i = 0; i < 8; i++) ra[i] = As[kk][tm + i];
#pragma unroll
            for (int j = 0; j < 8; j++) rb[j] = Bs[kk][tn + j];
#pragma unroll
            for (int i = 0; i < 8; i++)
#pragma unroll
                for (int j = 0; j < 8; j++)
                    acc[i][j] = fmaf(ra[i], rb[j], acc[i][j]);
        }
    }

#pragma unroll
    for (int i = 0; i < 8; i++) {
        int r = rowBase + tm + i;
        if (r < Mrows) {
            float* cp = C + (size_t)r * Ncols + colBase + tn;
#pragma unroll
            for (int j = 0; j < 8; j++) {
                int cc = colBase + tn + j;
                if (cc < Ncols) cp[j] = acc[i][j] + bias[cc];
            }
        }
    }
}

// ---------------- per-column mean/var partial sums --------------------------
__global__ void k_colstats(const float* __restrict__ H,
                           float* __restrict__ sum, float* __restrict__ sq) {
    int t = threadIdx.x;  // one column per thread (HF == blockDim == 256)
    int per = (NN + gridDim.x - 1) / gridDim.x;
    int r0 = blockIdx.x * per;
    int r1 = min(NN, r0 + per);
    float s = 0.f, q = 0.f;
    for (int r = r0; r < r1; r++) {
        float v = H[(size_t)r * HF + t];
        s += v;
        q = fmaf(v, v, q);
    }
    atomicAdd(&sum[t], s);
    atomicAdd(&sq[t], q);
}

__global__ void k_finalize(const float* __restrict__ sum,
                           const float* __restrict__ sq,
                           const float* __restrict__ gam,
                           const float* __restrict__ bet,
                           float* __restrict__ a, float* __restrict__ c) {
    int t = threadIdx.x;
    const float invN = 1.0f / (float)NN;
    float mean = sum[t] * invN;
    float var  = sq[t] * invN - mean * mean;   // biased var, matches jnp.var
    float inv  = rsqrtf(var + EPSV);
    float aa   = gam[t] * inv;
    a[t] = aa;
    c[t] = bet[t] - mean * aa;
}

// ---------------- labels (argmax of one-hot) + counts -----------------------
__global__ void k_labels(const float* __restrict__ cid,
                         int* __restrict__ labels, int* __restrict__ cnt) {
    int m = blockIdx.x * blockDim.x + threadIdx.x;
    if (m >= MM) return;
    const float* row = cid + (size_t)m * KC;
    int best = 0;
    float bv = row[0];
#pragma unroll
    for (int k = 1; k < KC; k++) {
        float v = row[k];
        if (v > bv) { bv = v; best = k; }  // strict > keeps first max (argmax semantics)
    }
    labels[m] = best;
    atomicAdd(&cnt[best], 1);
}

// ---------------- xc = relu(a2*H2[ci[m]] + c2) ------------------------------
__global__ void k_make_xc(const float* __restrict__ H2,
                          const int* __restrict__ ci,
                          const float* __restrict__ a2,
                          const float* __restrict__ c2,
                          float* __restrict__ XC) {
    int idx = blockIdx.x * blockDim.x + threadIdx.x;  // one float4 each
    if (idx >= MM * (HF / 4)) return;
    int m  = idx >> 6;            // HF/4 = 64
    int j4 = (idx & 63) * 4;
    int r  = ci[m];
    float4 v = *(const float4*)(H2 + (size_t)r * HF + j4);
    float4 a = *(const float4*)(a2 + j4);
    float4 c = *(const float4*)(c2 + j4);
    float4 o;
    o.x = fmaxf(fmaf(a.x, v.x, c.x), 0.f);
    o.y = fmaxf(fmaf(a.y, v.y, c.y), 0.f);
    o.z = fmaxf(fmaf(a.z, v.z, c.z), 0.f);
    o.w = fmaxf(fmaf(a.w, v.w, c.w), 0.f);
    *(float4*)(XC + (size_t)m * HF + j4) = o;
}

// ---------------- segment-sum (cluster feature sums) ------------------------
__global__ void k_cluster_accum(const float* __restrict__ XC,
                                const int* __restrict__ labels,
                                float* __restrict__ CFsum) {
    __shared__ float acc[KC * HF];   // 40 KB
    int t = threadIdx.x;
    for (int i = t; i < KC * HF; i += blockDim.x) acc[i] = 0.f;
    __syncthreads();
    int per = (MM + gridDim.x - 1) / gridDim.x;
    int m0 = blockIdx.x * per;
    int m1 = min(MM, m0 + per);
    for (int m = m0; m < m1; m++) {
        int lab = labels[m];                       // broadcast
        acc[lab * HF + t] += XC[(size_t)m * HF + t];
    }
    __syncthreads();
    for (int i = t; i < KC * HF; i += blockDim.x) atomicAdd(&CFsum[i], acc[i]);
}

// ---------------- P tables: PA = CF@WfcA^T + bfc, PB = CF@WfcB^T + bfc ------
__global__ void k_ptab(const float* __restrict__ Wfc,
                       const float* __restrict__ bfc,
                       const float* __restrict__ CFsum,
                       const int* __restrict__ cnt,
                       float* __restrict__ PA, float* __restrict__ PB) {
    __shared__ float cf[HF];
    int k = blockIdx.y;
    int t = threadIdx.x;
    float cnv = (float)cnt[k];
    cf[t] = CFsum[k * HF + t] / cnv;   // segment mean (matches onehot^T@xc / counts)
    __syncthreads();
    int o = blockIdx.x * 256 + t;
    const float* w = Wfc + (size_t)o * (2 * HF);
    float sa = 0.f, sb = 0.f;
#pragma unroll 4
    for (int j = 0; j < HF; j++) {
        float c = cf[j];
        sa = fmaf(c, w[j], sa);
        sb = fmaf(c, w[HF + j], sb);
    }
    float bb = bfc[o];
    PA[k * O2 + o] = sa + bb;
    PB[k * O2 + o] = sb + bb;
}

// ---------------- final GEMM + table epilogue -------------------------------
// gridDim.x = 16: tiles 0..7  -> XC@WfcA^T, out rows [0,M),   add PB[label]
//                 tiles 8..15 -> XC@WfcB^T, out rows [M,2M),  add PA[label]
__global__ void __launch_bounds__(256, 2)
k_gemm3(const float* __restrict__ XC, const float* __restrict__ Wfc,
        const int* __restrict__ labels,
        const float* __restrict__ PA, const float* __restrict__ PB,
        float* __restrict__ out) {
    __shared__ float As[8][128];
    __shared__ float Bs[8][128];

    const int tx = threadIdx.x;
    const int half = blockIdx.x >> 3;              // 0 -> A half, 1 -> B half
    const int colBase = (blockIdx.x & 7) * 128;    // within [0,1024)
    const int rowBase = blockIdx.y * 128;
    const int lr = tx >> 1;
    const int lc = (tx & 1) * 4;
    const int tm = (tx >> 4) * 8;
    const int tn = (tx & 15) * 8;

    float acc[8][8];
#pragma unroll
    for (int i = 0; i < 8; i++)
#pragma unroll
        for (int j = 0; j < 8; j++) acc[i][j] = 0.f;

    const int aRow = rowBase + lr;
    const int bRow = colBase + lr;                 // always < 1024
    const float* Aptr = XC + (size_t)aRow * HF;
    const float* Bptr = Wfc + (size_t)bRow * (2 * HF) + half * HF;

    for (int k0 = 0; k0 < HF; k0 += 8) {
        float4 av = make_float4(0.f, 0.f, 0.f, 0.f);
        if (aRow < MM) av = *(const float4*)(Aptr + k0 + lc);
        float4 bv = *(const float4*)(Bptr + k0 + lc);
        __syncthreads();
        As[lc + 0][lr] = av.x; As[lc + 1][lr] = av.y;
        As[lc + 2][lr] = av.z; As[lc + 3][lr] = av.w;
        Bs[lc + 0][lr] = bv.x; Bs[lc + 1][lr] = bv.y;
        Bs[lc + 2][lr] = bv.z; Bs[lc + 3][lr] = bv.w;
        __syncthreads();
#pragma unroll
        for (int kk = 0; kk < 8; kk++) {
            float ra[8], rb[8];
#pragma unroll
            for (int i = 0; i < 8; i++) ra[i] = As[kk][tm + i];
#pragma unroll
            for (int j = 0; j < 8; j++) rb[j] = Bs[kk][tn + j];
#pragma unroll
            for (int i = 0; i < 8; i++)
#pragma unroll
                for (int j = 0; j < 8; j++)
                    acc[i][j] = fmaf(ra[i], rb[j], acc[i][j]);
        }
    }

    const float* PX = half ? PA : PB;
    const size_t rowOff = half ? (size_t)MM : 0;
#pragma unroll
    for (int i = 0; i < 8; i++) {
        int r = rowBase + tm + i;
        if (r < MM) {
            int lab = labels[r];
            const float* px = PX + (size_t)lab * O2 + colBase + tn;
            float* op = out + ((size_t)r + rowOff) * O2 + colBase + tn;
#pragma unroll
            for (int j = 0; j < 8; j++) op[j] = acc[i][j] + px[j];
        }
    }
}

// ---------------- host launcher ---------------------------------------------
extern "C" void kernel_launch(void* const* d_in, const int* in_sizes, int n_in,
                              void* d_out, int out_size) {
    const float* x    = (const float*)d_in[0];
    const float* cid  = (const float*)d_in[1];
    const int*   cidx = (const int*)  d_in[2];
    const float* W1   = (const float*)d_in[3];
    const float* b1   = (const float*)d_in[4];
    const float* g1   = (const float*)d_in[5];
    const float* be1  = (const float*)d_in[6];
    const float* W2   = (const float*)d_in[7];
    const float* b2   = (const float*)d_in[8];
    const float* g2   = (const float*)d_in[9];
    const float* be2  = (const float*)d_in[10];
    const float* Wfc  = (const float*)d_in[11];
    const float* bfc  = (const float*)d_in[12];
    float* out = (float*)d_out;

    // Resolve scratch symbol addresses once (first call = correctness run,
    // so the captured graph contains only kernel launches).
    static float *H1 = nullptr, *H2, *XC, *sum1, *sq1, *a1, *c1,
                 *sum2, *sq2, *a2, *c2, *CFs, *PA, *PB;
    static int *cnt, *labs;
    if (!H1) {
        cudaGetSymbolAddress((void**)&H1,   g_H1);
        cudaGetSymbolAddress((void**)&H2,   g_H2);
        cudaGetSymbolAddress((void**)&XC,   g_XC);
        cudaGetSymbolAddress((void**)&sum1, g_sum1);
        cudaGetSymbolAddress((void**)&sq1,  g_sq1);
        cudaGetSymbolAddress((void**)&a1,   g_a1);
        cudaGetSymbolAddress((void**)&c1,   g_c1);
        cudaGetSymbolAddress((void**)&sum2, g_sum2);
        cudaGetSymbolAddress((void**)&sq2,  g_sq2);
        cudaGetSymbolAddress((void**)&a2,   g_a2);
        cudaGetSymbolAddress((void**)&c2,   g_c2);
        cudaGetSymbolAddress((void**)&CFs,  g_CFsum);
        cudaGetSymbolAddress((void**)&PA,   g_PA);
        cudaGetSymbolAddress((void**)&PB,   g_PB);
        cudaGetSymbolAddress((void**)&cnt,  g_counts);
        cudaGetSymbolAddress((void**)&labs, g_labels);
    }

    // 0) zero accumulators
    k_zero<<<40, 256>>>(sum1, sq1, sum2, sq2, CFs, cnt);

    // 1) H1raw = x @ W1^T + b1
    {
        dim3 grid(cdiv_h(HF, 128), cdiv_h(NN, 128));
        k_gemm_tn<false><<<grid, 256>>>(x, W1, b1, H1, NN, HF, D_IN,
                                        nullptr, nullptr);
    }
    // 2) BN1 stats -> (a1, c1)
    k_colstats<<<512, 256>>>(H1, sum1, sq1);
    k_finalize<<<1, 256>>>(sum1, sq1, g1, be1, a1, c1);

    // 3) H2raw = relu(a1*H1 + c1) @ W2^T + b2
    {
        dim3 grid(cdiv_h(HF, 128), cdiv_h(NN, 128));
        k_gemm_tn<true><<<grid, 256>>>(H1, W2, b2, H2, NN, HF, HF, a1, c1);
    }
    // 4) BN2 stats -> (a2, c2)
    k_colstats<<<512, 256>>>(H2, sum2, sq2);
    k_finalize<<<1, 256>>>(sum2, sq2, g2, be2, a2, c2);

    // 5) labels + counts
    k_labels<<<cdiv_h(MM, 256), 256>>>(cid, labs, cnt);

    // 6) XC = relu(a2 * H2[cidx] + c2)
    k_make_xc<<<cdiv_h(MM * (HF / 4), 256), 256>>>(H2, cidx, a2, c2, XC);

    // 7) cluster feature sums
    k_cluster_accum<<<256, 256>>>(XC, labs, CFs);

    // 8) PA/PB tables (includes segment-mean divide and +bfc)
    {
        dim3 grid(O2 / 256, KC);
        k_ptab<<<grid, 256>>>(Wfc, bfc, CFs, cnt, PA, PB);
    }

    // 9) final GEMM + epilogue writes the full [2M, 1024] output
    {
        dim3 grid(16, cdiv_h(MM, 128));
        k_gemm3<<<grid, 256>>>(XC, Wfc, labs, PA, PB, out);
    }
}

// round 7
// speedup vs baseline: 1.7976x; 1.7976x over previous
#include <cuda_runtime.h>
#include <cuda_bf16.h>
#include <cstdint>

// ---------------- problem constants ----------------------------------------
#define NN   100000   // batch rows
#define D_IN 500      // input features
#define KP1  512      // D_IN padded to MMA K granularity
#define HF   256      // hidden
#define MM   50000    // cluster rows
#define KC   40       // clusters
#define O2   1024     // OUT*OUT
#define EPSV 1e-5f

static inline int cdiv_h(int a, int b) { return (a + b - 1) / b; }

// ---------------- device scratch --------------------------------------------
__device__ float g_H1[(size_t)NN * HF];
__device__ float g_H2[(size_t)NN * HF];
__device__ float g_XC[(size_t)MM * HF];
__device__ float g_sum1[HF], g_sq1[HF], g_a1[HF], g_c1[HF];
__device__ float g_sum2[HF], g_sq2[HF], g_a2[HF], g_c2[HF];
__device__ float g_CFsum[KC * HF];
__device__ int   g_counts[KC];
__device__ int   g_labels[MM];
__device__ float g_PA[KC * O2];
__device__ float g_PB[KC * O2];

// bf16 split operands (hi + lo ~= fp32)
__device__ __nv_bfloat16 g_xhi[(size_t)NN * KP1];
__device__ __nv_bfloat16 g_xlo[(size_t)NN * KP1];
__device__ __nv_bfloat16 g_W1hi[(size_t)HF * KP1];
__device__ __nv_bfloat16 g_W1lo[(size_t)HF * KP1];
__device__ __nv_bfloat16 g_A2hi[(size_t)NN * HF];
__device__ __nv_bfloat16 g_A2lo[(size_t)NN * HF];
__device__ __nv_bfloat16 g_W2hi[(size_t)HF * HF];
__device__ __nv_bfloat16 g_W2lo[(size_t)HF * HF];
__device__ __nv_bfloat16 g_XChi[(size_t)MM * HF];
__device__ __nv_bfloat16 g_XClo[(size_t)MM * HF];
__device__ __nv_bfloat16 g_WChi[(size_t)2048 * HF];
__device__ __nv_bfloat16 g_WClo[(size_t)2048 * HF];

// ---------------- low-level helpers (all plain-sm_103-legal) ----------------
__device__ __forceinline__ uint32_t smem_u32(const void* p) {
    uint32_t a;
    asm("{ .reg .u64 t; cvta.to.shared.u64 t, %1; cvt.u32.u64 %0, t; }"
        : "=r"(a) : "l"(p));
    return a;
}

__device__ __forceinline__ void cp16(uint32_t saddr, const void* g, int sz) {
    asm volatile("cp.async.cg.shared.global [%0], [%1], 16, %2;"
                 :: "r"(saddr), "l"(g), "r"(sz) : "memory");
}
#define CP_COMMIT() asm volatile("cp.async.commit_group;" ::: "memory")
#define CP_WAIT(n)  asm volatile("cp.async.wait_group %0;" :: "n"(n) : "memory")

__device__ __forceinline__ void ldsm4(uint32_t* r, uint32_t addr) {
    asm volatile("ldmatrix.sync.aligned.m8n8.x4.shared.b16 {%0,%1,%2,%3}, [%4];"
                 : "=r"(r[0]), "=r"(r[1]), "=r"(r[2]), "=r"(r[3]) : "r"(addr));
}

__device__ __forceinline__ void mma16816(float* d, const uint32_t* a,
                                         uint32_t b0, uint32_t b1) {
    asm volatile(
        "mma.sync.aligned.m16n8k16.row.col.f32.bf16.bf16.f32 "
        "{%0,%1,%2,%3}, {%4,%5,%6,%7}, {%8,%9}, {%0,%1,%2,%3};"
        : "+f"(d[0]), "+f"(d[1]), "+f"(d[2]), "+f"(d[3])
        : "r"(a[0]), "r"(a[1]), "r"(a[2]), "r"(a[3]), "r"(b0), "r"(b1));
}

// ---------------- SMEM layout for the MMA GEMM ------------------------------
// Tiles are 128 rows x 32 bf16, rows padded to 40 bf16 (80 B) for
// conflict-free ldmatrix. 4 tiles (Ahi, Alo, Bhi, Blo) per stage, 2 stages.
#define LDSB   80                       // bytes per SMEM tile row
#define TILE_B (128 * LDSB)             // 10240
#define STG_B  (4 * TILE_B)             // 40960
#define SMEM_MMA (2 * STG_B)            // 81920

__device__ __forceinline__ void load_stage(
    uint32_t sb, int s,
    const __nv_bfloat16* __restrict__ Ahi, const __nv_bfloat16* __restrict__ Alo,
    const __nv_bfloat16* __restrict__ Bhi, const __nv_bfloat16* __restrict__ Blo,
    int rowBase, int Mrows, int colBase, int Ncols, int stride, int kB, int tx) {
    uint32_t st = sb + (uint32_t)s * STG_B;
#pragma unroll
    for (int h = 0; h < 2; h++) {
        int vid = tx + h * 256;          // 0..511
        int row = vid >> 2;              // 0..127
        int c16 = vid & 3;               // 16B chunk within the 64B K-slice
        uint32_t soff = (uint32_t)row * LDSB + (uint32_t)c16 * 16;
        long long ga = (long long)(rowBase + row) * stride + kB + c16 * 8;
        int vA = (rowBase + row < Mrows) ? 16 : 0;
        cp16(st + 0 * TILE_B + soff, Ahi + ga, vA);
        cp16(st + 1 * TILE_B + soff, Alo + ga, vA);
        long long gb = (long long)(colBase + row) * stride + kB + c16 * 8;
        int vB = (colBase + row < Ncols) ? 16 : 0;
        cp16(st + 2 * TILE_B + soff, Bhi + gb, vB);
        cp16(st + 3 * TILE_B + soff, Blo + gb, vB);
    }
}

// ---------------- tensor-core GEMM (mma.sync, split-bf16, 3 terms) ----------
// C[Mrows, Ncols] = (Ahi+Alo) @ (Bhi+Blo)^T   (lo*lo dropped)
// MODE 0: C[row*Ncols + col] = acc + bias[col]
// MODE 1: layer-3 epilogue: +PB/PA[label] table, 2M-row output layout
template <int MODE>
__global__ void __launch_bounds__(256)
k_mma(const __nv_bfloat16* __restrict__ Ahi, const __nv_bfloat16* __restrict__ Alo,
      const __nv_bfloat16* __restrict__ Bhi, const __nv_bfloat16* __restrict__ Blo,
      int Mrows, int Ncols, int K, int stride,
      const float* __restrict__ bias, float* __restrict__ Cmat,
      const int* __restrict__ labels, const float* __restrict__ PA,
      const float* __restrict__ PB, float* __restrict__ out) {
    extern __shared__ unsigned char smem[];
    const uint32_t sb = smem_u32(smem);
    const int tx = threadIdx.x;
    const int lane = tx & 31, wid = tx >> 5;
    const int warpM = wid & 3;           // 4 warps over M (32 rows each)
    const int warpN = wid >> 2;          // 2 warps over N (64 cols each)
    const int rowBase = blockIdx.y * 128;
    const int colBase = blockIdx.x * 128;

    float acc[2][8][4];
#pragma unroll
    for (int i = 0; i < 2; i++)
#pragma unroll
        for (int j = 0; j < 8; j++)
#pragma unroll
            for (int q = 0; q < 4; q++) acc[i][j][q] = 0.f;

    // prefetch stage 0
    load_stage(sb, 0, Ahi, Alo, Bhi, Blo, rowBase, Mrows, colBase, Ncols,
               stride, 0, tx);
    CP_COMMIT();

    const int C = K >> 5;    // BK = 32
    for (int c = 0; c < C; c++) {
        const int s = c & 1;
        if (c + 1 < C) {
            load_stage(sb, s ^ 1, Ahi, Alo, Bhi, Blo, rowBase, Mrows,
                       colBase, Ncols, stride, (c + 1) << 5, tx);
            CP_COMMIT();
            CP_WAIT(1);
        } else {
            CP_WAIT(0);
        }
        __syncthreads();
        const uint32_t stg = sb + (uint32_t)s * STG_B;
#pragma unroll
        for (int ks = 0; ks < 2; ks++) {
            const int k0 = ks * 16;
            uint32_t ah[2][4], al[2][4];
#pragma unroll
            for (int mf = 0; mf < 2; mf++) {
                uint32_t off =
                    (uint32_t)(warpM * 32 + mf * 16 + (lane & 15)) * LDSB +
                    (uint32_t)(k0 + (lane >> 4) * 8) * 2;
                ldsm4(ah[mf], stg + 0 * TILE_B + off);
                ldsm4(al[mf], stg + 1 * TILE_B + off);
            }
            const int grp = lane >> 3, rin = lane & 7;
#pragma unroll
            for (int p = 0; p < 4; p++) {
                uint32_t off =
                    (uint32_t)(warpN * 64 + p * 16 + (grp >> 1) * 8 + rin) * LDSB +
                    (uint32_t)(k0 + (grp & 1) * 8) * 2;
                uint32_t bh[4], bl[4];
                ldsm4(bh, stg + 2 * TILE_B + off);
                ldsm4(bl, stg + 3 * TILE_B + off);
#pragma unroll
                for (int mf = 0; mf < 2; mf++) {
                    mma16816(acc[mf][2 * p + 0], ah[mf], bh[0], bh[1]);
                    mma16816(acc[mf][2 * p + 0], ah[mf], bl[0], bl[1]);
                    mma16816(acc[mf][2 * p + 0], al[mf], bh[0], bh[1]);
                    mma16816(acc[mf][2 * p + 1], ah[mf], bh[2], bh[3]);
                    mma16816(acc[mf][2 * p + 1], ah[mf], bl[2], bl[3]);
                    mma16816(acc[mf][2 * p + 1], al[mf], bh[2], bh[3]);
                }
            }
        }
        __syncthreads();
    }

    // ---------------- epilogue ----------------
    // acc fragment layout: d0,d1 -> row (lane>>2), cols 2*(lane&3)+{0,1};
    //                      d2,d3 -> row (lane>>2)+8.
#pragma unroll
    for (int mf = 0; mf < 2; mf++) {
#pragma unroll
        for (int half = 0; half < 2; half++) {
            const int r = rowBase + warpM * 32 + mf * 16 + (lane >> 2) + half * 8;
            if (r >= Mrows) continue;
            if (MODE == 0) {
                float* cp = Cmat + (size_t)r * Ncols;
#pragma unroll
                for (int nf = 0; nf < 8; nf++) {
                    const int cc = colBase + warpN * 64 + nf * 8 + (lane & 3) * 2;
                    float2 b = *(const float2*)(bias + cc);
                    float2 v;
                    v.x = acc[mf][nf][half * 2 + 0] + b.x;
                    v.y = acc[mf][nf][half * 2 + 1] + b.y;
                    *(float2*)(cp + cc) = v;
                }
            } else {
                const bool hB = colBase >= 1024;   // Wcat rows >=1024 = WfcB half
                const int lab = labels[r];
                const float* P = hB ? PA : PB;
                const float* pl = P + (size_t)lab * O2;
                float* op = out + ((size_t)r + (hB ? (size_t)MM : 0)) * O2;
                const int cB = (colBase & 1023) + warpN * 64;
#pragma unroll
                for (int nf = 0; nf < 8; nf++) {
                    const int col = cB + nf * 8 + (lane & 3) * 2;
                    float2 p = *(const float2*)(pl + col);
                    float2 v;
                    v.x = acc[mf][nf][half * 2 + 0] + p.x;
                    v.y = acc[mf][nf][half * 2 + 1] + p.y;
                    *(float2*)(op + col) = v;
                }
            }
        }
    }
}

// ---------------- split / conversion kernels --------------------------------
__global__ void k_split(const float* __restrict__ src,
                        __nv_bfloat16* __restrict__ hi, __nv_bfloat16* __restrict__ lo,
                        int cols, int colsPad, long long total) {
    long long idx = blockIdx.x * (long long)blockDim.x + threadIdx.x;
    if (idx >= total) return;
    int r = (int)(idx / colsPad), c = (int)(idx % colsPad);
    float v = (c < cols) ? src[(size_t)r * cols + c] : 0.f;
    __nv_bfloat16 h = __float2bfloat16(v);
    hi[idx] = h;
    lo[idx] = __float2bfloat16(v - __bfloat162float(h));
}

__global__ void k_split_aff(const float* __restrict__ src,
                            const float* __restrict__ aa, const float* __restrict__ cc,
                            __nv_bfloat16* __restrict__ hi, __nv_bfloat16* __restrict__ lo,
                            long long total) {
    long long idx = blockIdx.x * (long long)blockDim.x + threadIdx.x;
    if (idx >= total) return;
    int c = (int)(idx & (HF - 1));
    float v = fmaxf(fmaf(aa[c], src[idx], cc[c]), 0.f);
    __nv_bfloat16 h = __float2bfloat16(v);
    hi[idx] = h;
    lo[idx] = __float2bfloat16(v - __bfloat162float(h));
}

// Wcat[2048,256]: rows 0..1023 = Wfc[:, :256]; rows 1024..2047 = Wfc[:, 256:]
__global__ void k_split_wcat(const float* __restrict__ Wfc,
                             __nv_bfloat16* __restrict__ hi,
                             __nv_bfloat16* __restrict__ lo) {
    int idx = blockIdx.x * blockDim.x + threadIdx.x;
    if (idx >= 2048 * HF) return;
    int o = idx >> 8, c = idx & 255;
    float v = (o < 1024) ? Wfc[(size_t)o * (2 * HF) + c]
                         : Wfc[(size_t)(o - 1024) * (2 * HF) + HF + c];
    __nv_bfloat16 h = __float2bfloat16(v);
    hi[idx] = h;
    lo[idx] = __float2bfloat16(v - __bfloat162float(h));
}

// ---------------- stats / labels / segment mean ------------------------------
__global__ void k_zero(float* s1, float* q1, float* s2, float* q2,
                       float* cfs, int* cnt) {
    int t = blockIdx.x * blockDim.x + threadIdx.x;
    if (t < HF) { s1[t] = 0.f; q1[t] = 0.f; s2[t] = 0.f; q2[t] = 0.f; }
    if (t < KC) cnt[t] = 0;
    if (t < KC * HF) cfs[t] = 0.f;
}

__global__ void k_colstats(const float* __restrict__ H,
                           float* __restrict__ sum, float* __restrict__ sq) {
    int t = threadIdx.x;
    int per = (NN + gridDim.x - 1) / gridDim.x;
    int r0 = blockIdx.x * per;
    int r1 = min(NN, r0 + per);
    float s = 0.f, q = 0.f;
    for (int r = r0; r < r1; r++) {
        float v = H[(size_t)r * HF + t];
        s += v;
        q = fmaf(v, v, q);
    }
    atomicAdd(&sum[t], s);
    atomicAdd(&sq[t], q);
}

__global__ void k_finalize(const float* __restrict__ sum, const float* __restrict__ sq,
                           const float* __restrict__ gam, const float* __restrict__ bet,
                           float* __restrict__ a, float* __restrict__ c) {
    int t = threadIdx.x;
    const float invN = 1.0f / (float)NN;
    float mean = sum[t] * invN;
    float var  = sq[t] * invN - mean * mean;
    float inv  = rsqrtf(var + EPSV);
    float aa   = gam[t] * inv;
    a[t] = aa;
    c[t] = bet[t] - mean * aa;
}

__global__ void k_labels(const float* __restrict__ cid,
                         int* __restrict__ labels, int* __restrict__ cnt) {
    int m = blockIdx.x * blockDim.x + threadIdx.x;
    if (m >= MM) return;
    const float* row = cid + (size_t)m * KC;
    int best = 0;
    float bv = row[0];
#pragma unroll
    for (int k = 1; k < KC; k++) {
        float v = row[k];
        if (v > bv) { bv = v; best = k; }
    }
    labels[m] = best;
    atomicAdd(&cnt[best], 1);
}

__global__ void k_make_xc(const float* __restrict__ H2, const int* __restrict__ ci,
                          const float* __restrict__ a2, const float* __restrict__ c2,
                          float* __restrict__ XC) {
    int idx = blockIdx.x * blockDim.x + threadIdx.x;
    if (idx >= MM * (HF / 4)) return;
    int m  = idx >> 6;
    int j4 = (idx & 63) * 4;
    int r  = ci[m];
    float4 v = *(const float4*)(H2 + (size_t)r * HF + j4);
    float4 a = *(const float4*)(a2 + j4);
    float4 c = *(const float4*)(c2 + j4);
    float4 o;
    o.x = fmaxf(fmaf(a.x, v.x, c.x), 0.f);
    o.y = fmaxf(fmaf(a.y, v.y, c.y), 0.f);
    o.z = fmaxf(fmaf(a.z, v.z, c.z), 0.f);
    o.w = fmaxf(fmaf(a.w, v.w, c.w), 0.f);
    *(float4*)(XC + (size_t)m * HF + j4) = o;
}

__global__ void k_cluster_accum(const float* __restrict__ XC,
                                const int* __restrict__ labels,
                                float* __restrict__ CFsum) {
    __shared__ float acc[KC * HF];
    int t = threadIdx.x;
    for (int i = t; i < KC * HF; i += blockDim.x) acc[i] = 0.f;
    __syncthreads();
    int per = (MM + gridDim.x - 1) / gridDim.x;
    int m0 = blockIdx.x * per;
    int m1 = min(MM, m0 + per);
    for (int m = m0; m < m1; m++) {
        int lab = labels[m];
        acc[lab * HF + t] += XC[(size_t)m * HF + t];
    }
    __syncthreads();
    for (int i = t; i < KC * HF; i += blockDim.x) atomicAdd(&CFsum[i], acc[i]);
}

__global__ void k_ptab(const float* __restrict__ Wfc, const float* __restrict__ bfc,
                       const float* __restrict__ CFsum, const int* __restrict__ cnt,
                       float* __restrict__ PA, float* __restrict__ PB) {
    __shared__ float cf[HF];
    int k = blockIdx.y;
    int t = threadIdx.x;
    float cnv = (float)cnt[k];
    cf[t] = CFsum[k * HF + t] / cnv;
    __syncthreads();
    int o = blockIdx.x * 256 + t;
    const float* w = Wfc + (size_t)o * (2 * HF);
    float sa = 0.f, sb = 0.f;
#pragma unroll 4
    for (int j = 0; j < HF; j++) {
        float c = cf[j];
        sa = fmaf(c, w[j], sa);
        sb = fmaf(c, w[HF + j], sb);
    }
    float bb = bfc[o];
    PA[k * O2 + o] = sa + bb;
    PB[k * O2 + o] = sb + bb;
}

// ---------------- host launcher ---------------------------------------------
extern "C" void kernel_launch(void* const* d_in, const int* in_sizes, int n_in,
                              void* d_out, int out_size) {
    const float* x    = (const float*)d_in[0];
    const float* cid  = (const float*)d_in[1];
    const int*   cidx = (const int*)  d_in[2];
    const float* W1   = (const float*)d_in[3];
    const float* b1   = (const float*)d_in[4];
    const float* g1   = (const float*)d_in[5];
    const float* be1  = (const float*)d_in[6];
    const float* W2   = (const float*)d_in[7];
    const float* b2   = (const float*)d_in[8];
    const float* g2   = (const float*)d_in[9];
    const float* be2  = (const float*)d_in[10];
    const float* Wfc  = (const float*)d_in[11];
    const float* bfc  = (const float*)d_in[12];
    float* out = (float*)d_out;

    static bool inited = false;
    static float *H1, *H2, *XC, *sum1, *sq1, *a1, *c1, *sum2, *sq2, *a2, *c2,
                 *CFs, *PA, *PB;
    static int *cnt, *labs;
    static __nv_bfloat16 *xhi, *xlo, *W1h, *W1l, *A2h, *A2l, *W2h, *W2l,
                         *XCh, *XCl, *WCh, *WCl;
    if (!inited) {
        inited = true;
        cudaGetSymbolAddress((void**)&H1,   g_H1);
        cudaGetSymbolAddress((void**)&H2,   g_H2);
        cudaGetSymbolAddress((void**)&XC,   g_XC);
        cudaGetSymbolAddress((void**)&sum1, g_sum1);
        cudaGetSymbolAddress((void**)&sq1,  g_sq1);
        cudaGetSymbolAddress((void**)&a1,   g_a1);
        cudaGetSymbolAddress((void**)&c1,   g_c1);
        cudaGetSymbolAddress((void**)&sum2, g_sum2);
        cudaGetSymbolAddress((void**)&sq2,  g_sq2);
        cudaGetSymbolAddress((void**)&a2,   g_a2);
        cudaGetSymbolAddress((void**)&c2,   g_c2);
        cudaGetSymbolAddress((void**)&CFs,  g_CFsum);
        cudaGetSymbolAddress((void**)&PA,   g_PA);
        cudaGetSymbolAddress((void**)&PB,   g_PB);
        cudaGetSymbolAddress((void**)&cnt,  g_counts);
        cudaGetSymbolAddress((void**)&labs, g_labels);
        cudaGetSymbolAddress((void**)&xhi,  g_xhi);
        cudaGetSymbolAddress((void**)&xlo,  g_xlo);
        cudaGetSymbolAddress((void**)&W1h,  g_W1hi);
        cudaGetSymbolAddress((void**)&W1l,  g_W1lo);
        cudaGetSymbolAddress((void**)&A2h,  g_A2hi);
        cudaGetSymbolAddress((void**)&A2l,  g_A2lo);
        cudaGetSymbolAddress((void**)&W2h,  g_W2hi);
        cudaGetSymbolAddress((void**)&W2l,  g_W2lo);
        cudaGetSymbolAddress((void**)&XCh,  g_XChi);
        cudaGetSymbolAddress((void**)&XCl,  g_XClo);
        cudaGetSymbolAddress((void**)&WCh,  g_WChi);
        cudaGetSymbolAddress((void**)&WCl,  g_WClo);
        cudaFuncSetAttribute(k_mma<0>,
                             cudaFuncAttributeMaxDynamicSharedMemorySize, SMEM_MMA);
        cudaFuncSetAttribute(k_mma<1>,
                             cudaFuncAttributeMaxDynamicSharedMemorySize, SMEM_MMA);
    }

    // 0) zero accumulators
    k_zero<<<40, 256>>>(sum1, sq1, sum2, sq2, CFs, cnt);

    // splits of constant weights
    {
        long long t1 = (long long)HF * KP1;
        k_split<<<cdiv_h((int)t1, 256), 256>>>(W1, W1h, W1l, D_IN, KP1, t1);
        long long t2 = (long long)HF * HF;
        k_split<<<cdiv_h((int)t2, 256), 256>>>(W2, W2h, W2l, HF, HF, t2);
        k_split_wcat<<<cdiv_h(2048 * HF, 256), 256>>>(Wfc, WCh, WCl);
    }
    // split x (padded K=512)
    {
        long long t = (long long)NN * KP1;
        k_split<<<(int)((t + 255) / 256), 256>>>(x, xhi, xlo, D_IN, KP1, t);
    }

    // 1) H1 = x @ W1^T + b1   (tensor cores, split-bf16)
    {
        dim3 grid(HF / 128, cdiv_h(NN, 128));
        k_mma<0><<<grid, 256, SMEM_MMA>>>(xhi, xlo, W1h, W1l,
            NN, HF, KP1, KP1, b1, H1, nullptr, nullptr, nullptr, nullptr);
    }
    // 2) BN1 stats
    k_colstats<<<512, 256>>>(H1, sum1, sq1);
    k_finalize<<<1, 256>>>(sum1, sq1, g1, be1, a1, c1);

    // 3) A2 = relu(a1*H1 + c1) split; H2 = A2 @ W2^T + b2
    {
        long long t = (long long)NN * HF;
        k_split_aff<<<(int)((t + 255) / 256), 256>>>(H1, a1, c1, A2h, A2l, t);
        dim3 grid(HF / 128, cdiv_h(NN, 128));
        k_mma<0><<<grid, 256, SMEM_MMA>>>(A2h, A2l, W2h, W2l,
            NN, HF, HF, HF, b2, H2, nullptr, nullptr, nullptr, nullptr);
    }
    // 4) BN2 stats
    k_colstats<<<512, 256>>>(H2, sum2, sq2);
    k_finalize<<<1, 256>>>(sum2, sq2, g2, be2, a2, c2);

    // 5) labels + counts
    k_labels<<<cdiv_h(MM, 256), 256>>>(cid, labs, cnt);

    // 6) XC = relu(a2 * H2[cidx] + c2); split
    k_make_xc<<<cdiv_h(MM * (HF / 4), 256), 256>>>(H2, cidx, a2, c2, XC);
    {
        long long t = (long long)MM * HF;
        k_split<<<(int)((t + 255) / 256), 256>>>(XC, XCh, XCl, HF, HF, t);
    }

    // 7) cluster feature sums
    k_cluster_accum<<<256, 256>>>(XC, labs, CFs);

    // 8) PA/PB tables
    {
        dim3 grid(O2 / 256, KC);
        k_ptab<<<grid, 256>>>(Wfc, bfc, CFs, cnt, PA, PB);
    }

    // 9) final GEMM: Y = XC @ Wcat^T, epilogue adds PB/PA and scatters rows
    {
        dim3 grid(2048 / 128, cdiv_h(MM, 128));
        k_mma<1><<<grid, 256, SMEM_MMA>>>(XCh, XCl, WCh, WCl,
            MM, 2048, HF, HF, nullptr, nullptr, labs, PA, PB, out);
    }
}

// round 8
// speedup vs baseline: 2.3172x; 1.2890x over previous
#include <cuda_runtime.h>
#include <cuda_bf16.h>
#include <cstdint>

// ---------------- problem constants ----------------------------------------
#define NN   100000   // batch rows
#define NNP  100096   // padded to 128
#define D_IN 500      // input features
#define KP1  512      // D_IN padded to MMA K granularity
#define HF   256      // hidden
#define MM   50000    // cluster rows
#define MMP  50048    // padded to 128
#define KC   40       // clusters
#define O2   1024     // OUT*OUT
#define EPSV 1e-5f

static inline int cdiv_h(int a, int b) { return (a + b - 1) / b; }

// ---------------- device scratch --------------------------------------------
__device__ float g_H1[(size_t)NN * HF];
__device__ float g_H2[(size_t)NN * HF];
__device__ float g_XC[(size_t)MM * HF];
__device__ float g_sum1[HF], g_sq1[HF], g_a1[HF], g_c1[HF];
__device__ float g_sum2[HF], g_sq2[HF], g_a2[HF], g_c2[HF];
__device__ float g_CFsum[KC * HF];
__device__ int   g_counts[KC];
__device__ int   g_labels[MM];
__device__ float g_PA[KC * O2];
__device__ float g_PB[KC * O2];

// Pre-tiled, SW128-swizzled bf16 operands (hi + lo ~= fp32).
// Layout: tile (rowTile, kTile) of 128x64 bf16 = 16 KB contiguous at
// ((rowTile*KT + kTile) << 13) elements; inside, SW128 swizzle.
__device__ __nv_bfloat16 g_xhi[(size_t)NNP * KP1];
__device__ __nv_bfloat16 g_xlo[(size_t)NNP * KP1];
__device__ __nv_bfloat16 g_W1hi[(size_t)HF * KP1];
__device__ __nv_bfloat16 g_W1lo[(size_t)HF * KP1];
__device__ __nv_bfloat16 g_A2hi[(size_t)NNP * HF];
__device__ __nv_bfloat16 g_A2lo[(size_t)NNP * HF];
__device__ __nv_bfloat16 g_W2hi[(size_t)HF * HF];
__device__ __nv_bfloat16 g_W2lo[(size_t)HF * HF];
__device__ __nv_bfloat16 g_XChi[(size_t)MMP * HF];
__device__ __nv_bfloat16 g_XClo[(size_t)MMP * HF];
__device__ __nv_bfloat16 g_WChi[(size_t)2048 * HF];
__device__ __nv_bfloat16 g_WClo[(size_t)2048 * HF];

// ---------------- low-level helpers ------------------------------------------
__device__ __forceinline__ uint32_t smem_u32(const void* p) {
    uint32_t a;
    asm("{ .reg .u64 t; cvta.to.shared.u64 t, %1; cvt.u32.u64 %0, t; }"
        : "=r"(a) : "l"(p));
    return a;
}

// Bulk async copy: one instruction per 16 KB tile (UBLKCP) + mbarrier tx.
__device__ __forceinline__ void bulkcp(uint32_t dst, const void* src,
                                       uint32_t bytes, uint32_t mbar) {
    asm volatile(
        "cp.async.bulk.shared::cluster.global.mbarrier::complete_tx::bytes "
        "[%0], [%1], %2, [%3];"
        :: "r"(dst), "l"(src), "r"(bytes), "r"(mbar) : "memory");
}

#define MBAR_INIT(addr, cnt) \
    asm volatile("mbarrier.init.shared.b64 [%0], %1;" \
                 :: "r"((uint32_t)(addr)), "r"((uint32_t)(cnt)) : "memory")
#define MBAR_EXPECT(addr, tx) \
    asm volatile("mbarrier.arrive.expect_tx.shared.b64 _, [%0], %1;" \
                 :: "r"((uint32_t)(addr)), "r"((uint32_t)(tx)) : "memory")
#define MBAR_WAIT(addr, parity) do {                                           \
    uint32_t _m = (uint32_t)(addr); uint32_t _p = (uint32_t)(parity);          \
    uint32_t _d;                                                               \
    asm volatile("{\n\t.reg .pred p;\n\t"                                      \
        "mbarrier.try_wait.parity.acquire.cta.shared::cta.b64 p, [%1], %2;\n\t"\
        "selp.b32 %0, 1, 0, p;\n\t}" : "=r"(_d) : "r"(_m), "r"(_p) : "memory");\
    if (!_d) {                                                                 \
        asm volatile("{\n\t.reg .pred P1;\n\t"                                 \
            "WL_%=:\n\t"                                                       \
            "mbarrier.try_wait.parity.acquire.cta.shared::cta.b64 P1, [%0], %1, 0x989680;\n\t" \
            "@P1 bra.uni WD_%=;\n\t"                                           \
            "bra.uni WL_%=;\n\t"                                               \
            "WD_%=:\n\t}" :: "r"(_m), "r"(_p) : "memory");                     \
    }                                                                          \
} while (0)

__device__ __forceinline__ void ldsm4(uint32_t* r, uint32_t addr) {
    asm volatile("ldmatrix.sync.aligned.m8n8.x4.shared.b16 {%0,%1,%2,%3}, [%4];"
                 : "=r"(r[0]), "=r"(r[1]), "=r"(r[2]), "=r"(r[3]) : "r"(addr));
}

__device__ __forceinline__ void mma16816(float* d, const uint32_t* a,
                                         uint32_t b0, uint32_t b1) {
    asm volatile(
        "mma.sync.aligned.m16n8k16.row.col.f32.bf16.bf16.f32 "
        "{%0,%1,%2,%3}, {%4,%5,%6,%7}, {%8,%9}, {%0,%1,%2,%3};"
        : "+f"(d[0]), "+f"(d[1]), "+f"(d[2]), "+f"(d[3])
        : "r"(a[0]), "r"(a[1]), "r"(a[2]), "r"(a[3]), "r"(b0), "r"(b1));
}

// Element offset inside the tiled+swizzled operand layout.
__device__ __forceinline__ size_t tileoff(int row, int k, int KT) {
    size_t base = ((size_t)((row >> 7) * KT + (k >> 6))) << 13;
    uint32_t boff = ((uint32_t)(row & 127) << 7) | ((uint32_t)(k & 63) << 1);
    uint32_t sw = boff ^ ((boff >> 3) & 0x70);
    return base + (sw >> 1);
}

__device__ __forceinline__ uint32_t swz(uint32_t boff) {
    return boff ^ ((boff >> 3) & 0x70);
}

// ---------------- bulk-loaded tensor-core GEMM ------------------------------
// C[MrowsTrue, Ncols] = (Ahi+Alo)[.,K] @ (Bhi+Blo)[Ncols,K]^T  (split-bf16,
// lo*lo dropped).  Operands pre-tiled 128x64 SW128 blocks.
// MODE 0: C[r*Ncols + c] = acc + bias[c]
// MODE 1: layer-3 epilogue: +PB/PA[label] table, 2M-row output layout
#define TILE16K 16384
#define STG64K  65536
#define NSTAGE  3
#define SMEM_GG (NSTAGE * STG64K + 32)   // + mbarriers

template <int MODE>
__global__ void __launch_bounds__(256)
k_bulkmma(const __nv_bfloat16* __restrict__ Ahi, const __nv_bfloat16* __restrict__ Alo,
          const __nv_bfloat16* __restrict__ Bhi, const __nv_bfloat16* __restrict__ Blo,
          int Mrows, int Ncols, int KT,
          const float* __restrict__ bias, float* __restrict__ Cmat,
          const int* __restrict__ labels, const float* __restrict__ PA,
          const float* __restrict__ PB, float* __restrict__ out) {
    extern __shared__ unsigned char smem[];
    const uint32_t sb = smem_u32(smem);
    const uint32_t mb = sb + NSTAGE * STG64K;   // 3 mbarriers, 8 B apart
    const int tx = threadIdx.x;
    const int lane = tx & 31, wid = tx >> 5;
    const int warpM = wid & 3;           // 4 warps over M (32 rows each)
    const int warpN = wid >> 2;          // 2 warps over N (64 cols each)
    const int rowBase = blockIdx.y * 128;
    const int colBase = blockIdx.x * 128;

    if (tx == 0) {
        MBAR_INIT(mb + 0, 1);
        MBAR_INIT(mb + 8, 1);
        MBAR_INIT(mb + 16, 1);
    }
    __syncthreads();

    const size_t aBase = ((size_t)blockIdx.y * KT) << 13;
    const size_t bBase = ((size_t)blockIdx.x * KT) << 13;

    // prologue: issue up to 3 chunks
    if (tx == 0) {
        const int pre = (KT < NSTAGE) ? KT : NSTAGE;
        for (int s = 0; s < pre; s++) {
            const size_t off = aBase + ((size_t)s << 13);
            const size_t bof = bBase + ((size_t)s << 13);
            MBAR_EXPECT(mb + 8 * s, STG64K);
            uint32_t d = sb + (uint32_t)s * STG64K;
            bulkcp(d + 0 * TILE16K, Ahi + off, TILE16K, mb + 8 * s);
            bulkcp(d + 1 * TILE16K, Alo + off, TILE16K, mb + 8 * s);
            bulkcp(d + 2 * TILE16K, Bhi + bof, TILE16K, mb + 8 * s);
            bulkcp(d + 3 * TILE16K, Blo + bof, TILE16K, mb + 8 * s);
        }
    }

    float acc[2][8][4];
#pragma unroll
    for (int i = 0; i < 2; i++)
#pragma unroll
        for (int j = 0; j < 8; j++)
#pragma unroll
            for (int q = 0; q < 4; q++) acc[i][j][q] = 0.f;

    int ph[NSTAGE] = {0, 0, 0};
    for (int c = 0; c < KT; c++) {
        const int s = c % NSTAGE;
        MBAR_WAIT(mb + 8 * s, ph[s]);
        ph[s] ^= 1;
        const uint32_t stg = sb + (uint32_t)s * STG64K;
#pragma unroll
        for (int ks = 0; ks < 4; ks++) {
            const int k0 = ks * 16;
            uint32_t ah[2][4], al[2][4];
#pragma unroll
            for (int mf = 0; mf < 2; mf++) {
                uint32_t boff = ((uint32_t)(warpM * 32 + mf * 16 + (lane & 15)) << 7) |
                                ((uint32_t)(k0 + (lane >> 4) * 8) << 1);
                uint32_t off = swz(boff);
                ldsm4(ah[mf], stg + 0 * TILE16K + off);
                ldsm4(al[mf], stg + 1 * TILE16K + off);
            }
            const int grp = lane >> 3, rin = lane & 7;
#pragma unroll
            for (int p = 0; p < 4; p++) {
                uint32_t boff = ((uint32_t)(warpN * 64 + p * 16 + (grp >> 1) * 8 + rin) << 7) |
                                ((uint32_t)(k0 + (grp & 1) * 8) << 1);
                uint32_t off = swz(boff);
                uint32_t bh[4], bl[4];
                ldsm4(bh, stg + 2 * TILE16K + off);
                ldsm4(bl, stg + 3 * TILE16K + off);
#pragma unroll
                for (int mf = 0; mf < 2; mf++) {
                    mma16816(acc[mf][2 * p + 0], ah[mf], bh[0], bh[1]);
                    mma16816(acc[mf][2 * p + 0], ah[mf], bl[0], bl[1]);
                    mma16816(acc[mf][2 * p + 0], al[mf], bh[0], bh[1]);
                    mma16816(acc[mf][2 * p + 1], ah[mf], bh[2], bh[3]);
                    mma16816(acc[mf][2 * p + 1], ah[mf], bl[2], bl[3]);
                    mma16816(acc[mf][2 * p + 1], al[mf], bh[2], bh[3]);
                }
            }
        }
        __syncthreads();   // all warps done with stage s before refill
        if (c + NSTAGE < KT && tx == 0) {
            const int cn = c + NSTAGE;
            const size_t off = aBase + ((size_t)cn << 13);
            const size_t bof = bBase + ((size_t)cn << 13);
            MBAR_EXPECT(mb + 8 * s, STG64K);
            uint32_t d = sb + (uint32_t)s * STG64K;
            bulkcp(d + 0 * TILE16K, Ahi + off, TILE16K, mb + 8 * s);
            bulkcp(d + 1 * TILE16K, Alo + off, TILE16K, mb + 8 * s);
            bulkcp(d + 2 * TILE16K, Bhi + bof, TILE16K, mb + 8 * s);
            bulkcp(d + 3 * TILE16K, Blo + bof, TILE16K, mb + 8 * s);
        }
    }

    // ---------------- epilogue (same fragment layout as R7, proven) ----------
#pragma unroll
    for (int mf = 0; mf < 2; mf++) {
#pragma unroll
        for (int half = 0; half < 2; half++) {
            const int r = rowBase + warpM * 32 + mf * 16 + (lane >> 2) + half * 8;
            if (r >= Mrows) continue;
            if (MODE == 0) {
                float* cp = Cmat + (size_t)r * Ncols;
#pragma unroll
                for (int nf = 0; nf < 8; nf++) {
                    const int cc = colBase + warpN * 64 + nf * 8 + (lane & 3) * 2;
                    float2 b = *(const float2*)(bias + cc);
                    float2 v;
                    v.x = acc[mf][nf][half * 2 + 0] + b.x;
                    v.y = acc[mf][nf][half * 2 + 1] + b.y;
                    *(float2*)(cp + cc) = v;
                }
            } else {
                const bool hB = colBase >= 1024;   // Wcat rows >=1024 = WfcB half
                const int lab = labels[r];
                const float* P = hB ? PA : PB;
                const float* pl = P + (size_t)lab * O2;
                float* op = out + ((size_t)r + (hB ? (size_t)MM : 0)) * O2;
                const int cB = (colBase & 1023) + warpN * 64;
#pragma unroll
                for (int nf = 0; nf < 8; nf++) {
                    const int col = cB + nf * 8 + (lane & 3) * 2;
                    float2 p = *(const float2*)(pl + col);
                    float2 v;
                    v.x = acc[mf][nf][half * 2 + 0] + p.x;
                    v.y = acc[mf][nf][half * 2 + 1] + p.y;
                    *(float2*)(op + col) = v;
                }
            }
        }
    }
}

// ---------------- split kernels: fp32 -> tiled swizzled bf16 hi/lo ----------
// One thread handles 8 consecutive k (one 16-B swizzled group).
__global__ void k_split_t(const float* __restrict__ src,
                          __nv_bfloat16* __restrict__ hi,
                          __nv_bfloat16* __restrict__ lo,
                          int rowsSrc, int colsSrc, int K8, int KT,
                          long long total) {
    long long idx = blockIdx.x * (long long)blockDim.x + threadIdx.x;
    if (idx >= total) return;
    int row = (int)(idx / K8);
    int k   = (int)(idx % K8) * 8;
    __nv_bfloat16 h8[8], l8[8];
#pragma unroll
    for (int j = 0; j < 8; j++) {
        float v = 0.f;
        if (row < rowsSrc && k + j < colsSrc)
            v = src[(size_t)row * colsSrc + k + j];
        __nv_bfloat16 h = __float2bfloat16(v);
        h8[j] = h;
        l8[j] = __float2bfloat16(v - __bfloat162float(h));
    }
    size_t off = tileoff(row, k, KT);
    *(uint4*)(hi + off) = *(uint4*)h8;
    *(uint4*)(lo + off) = *(uint4*)l8;
}

__global__ void k_split_aff_t(const float* __restrict__ src,
                              const float* __restrict__ aa, const float* __restrict__ cc,
                              __nv_bfloat16* __restrict__ hi,
                              __nv_bfloat16* __restrict__ lo,
                              int rowsSrc, long long total) {
    long long idx = blockIdx.x * (long long)blockDim.x + threadIdx.x;
    if (idx >= total) return;
    int row = (int)(idx / (HF / 8));
    int k   = (int)(idx % (HF / 8)) * 8;
    __nv_bfloat16 h8[8], l8[8];
#pragma unroll
    for (int j = 0; j < 8; j++) {
        float v = 0.f;
        if (row < rowsSrc) {
            v = fmaxf(fmaf(aa[k + j], src[(size_t)row * HF + k + j], cc[k + j]), 0.f);
        }
        __nv_bfloat16 h = __float2bfloat16(v);
        h8[j] = h;
        l8[j] = __float2bfloat16(v - __bfloat162float(h));
    }
    size_t off = tileoff(row, k, HF / 64);
    *(uint4*)(hi + off) = *(uint4*)h8;
    *(uint4*)(lo + off) = *(uint4*)l8;
}

// Wcat[2048,256]: rows 0..1023 = Wfc[:, :256]; rows 1024..2047 = Wfc[:, 256:]
__global__ void k_split_wcat_t(const float* __restrict__ Wfc,
                               __nv_bfloat16* __restrict__ hi,
                               __nv_bfloat16* __restrict__ lo) {
    int idx = blockIdx.x * blockDim.x + threadIdx.x;   // 2048 * 32 groups
    if (idx >= 2048 * (HF / 8)) return;
    int o = idx / (HF / 8);
    int k = (idx % (HF / 8)) * 8;
    const float* w = (o < 1024) ? (Wfc + (size_t)o * (2 * HF))
                                : (Wfc + (size_t)(o - 1024) * (2 * HF) + HF);
    __nv_bfloat16 h8[8], l8[8];
#pragma unroll
    for (int j = 0; j < 8; j++) {
        float v = w[k + j];
        __nv_bfloat16 h = __float2bfloat16(v);
        h8[j] = h;
        l8[j] = __float2bfloat16(v - __bfloat162float(h));
    }
    size_t off = tileoff(o, k, HF / 64);
    *(uint4*)(hi + off) = *(uint4*)h8;
    *(uint4*)(lo + off) = *(uint4*)l8;
}

// ---------------- stats / labels / segment mean (unchanged, proven) ---------
__global__ void k_zero(float* s1, float* q1, float* s2, float* q2,
                       float* cfs, int* cnt) {
    int t = blockIdx.x * blockDim.x + threadIdx.x;
    if (t < HF) { s1[t] = 0.f; q1[t] = 0.f; s2[t] = 0.f; q2[t] = 0.f; }
    if (t < KC) cnt[t] = 0;
    if (t < KC * HF) cfs[t] = 0.f;
}

__global__ void k_colstats(const float* __restrict__ H,
                           float* __restrict__ sum, float* __restrict__ sq) {
    int t = threadIdx.x;
    int per = (NN + gridDim.x - 1) / gridDim.x;
    int r0 = blockIdx.x * per;
    int r1 = min(NN, r0 + per);
    float s = 0.f, q = 0.f;
    for (int r = r0; r < r1; r++) {
        float v = H[(size_t)r * HF + t];
        s += v;
        q = fmaf(v, v, q);
    }
    atomicAdd(&sum[t], s);
    atomicAdd(&sq[t], q);
}

__global__ void k_finalize(const float* __restrict__ sum, const float* __restrict__ sq,
                           const float* __restrict__ gam, const float* __restrict__ bet,
                           float* __restrict__ a, float* __restrict__ c) {
    int t = threadIdx.x;
    const float invN = 1.0f / (float)NN;
    float mean = sum[t] * invN;
    float var  = sq[t] * invN - mean * mean;
    float inv  = rsqrtf(var + EPSV);
    float aa   = gam[t] * inv;
    a[t] = aa;
    c[t] = bet[t] - mean * aa;
}

__global__ void k_labels(const float* __restrict__ cid,
                         int* __restrict__ labels, int* __restrict__ cnt) {
    int m = blockIdx.x * blockDim.x + threadIdx.x;
    if (m >= MM) return;
    const float* row = cid + (size_t)m * KC;
    int best = 0;
    float bv = row[0];
#pragma unroll
    for (int k = 1; k < KC; k++) {
        float v = row[k];
        if (v > bv) { bv = v; best = k; }
    }
    labels[m] = best;
    atomicAdd(&cnt[best], 1);
}

// XC = relu(a2*H2[ci[m]] + c2): fp32 copy (for cluster sums) + tiled split
__global__ void k_make_xc(const float* __restrict__ H2, const int* __restrict__ ci,
                          const float* __restrict__ a2, const float* __restrict__ c2,
                          float* __restrict__ XC,
                          __nv_bfloat16* __restrict__ hi,
                          __nv_bfloat16* __restrict__ lo) {
    int idx = blockIdx.x * blockDim.x + threadIdx.x;   // MMP * 32 groups of 8
    if (idx >= MMP * (HF / 8)) return;
    int m = idx / (HF / 8);
    int k = (idx % (HF / 8)) * 8;
    __nv_bfloat16 h8[8], l8[8];
    float o8[8];
#pragma unroll
    for (int j = 0; j < 8; j++) o8[j] = 0.f;
    if (m < MM) {
        int r = ci[m];
        const float* hp = H2 + (size_t)r * HF + k;
#pragma unroll
        for (int j = 0; j < 8; j++)
            o8[j] = fmaxf(fmaf(a2[k + j], hp[j], c2[k + j]), 0.f);
        float4* xp = (float4*)(XC + (size_t)m * HF + k);
        xp[0] = make_float4(o8[0], o8[1], o8[2], o8[3]);
        xp[1] = make_float4(o8[4], o8[5], o8[6], o8[7]);
    }
#pragma unroll
    for (int j = 0; j < 8; j++) {
        __nv_bfloat16 h = __float2bfloat16(o8[j]);
        h8[j] = h;
        l8[j] = __float2bfloat16(o8[j] - __bfloat162float(h));
    }
    size_t off = tileoff(m, k, HF / 64);
    *(uint4*)(hi + off) = *(uint4*)h8;
    *(uint4*)(lo + off) = *(uint4*)l8;
}

__global__ void k_cluster_accum(const float* __restrict__ XC,
                                const int* __restrict__ labels,
                                float* __restrict__ CFsum) {
    __shared__ float acc[KC * HF];
    int t = threadIdx.x;
    for (int i = t; i < KC * HF; i += blockDim.x) acc[i] = 0.f;
    __syncthreads();
    int per = (MM + gridDim.x - 1) / gridDim.x;
    int m0 = blockIdx.x * per;
    int m1 = min(MM, m0 + per);
    for (int m = m0; m < m1; m++) {
        int lab = labels[m];
        acc[lab * HF + t] += XC[(size_t)m * HF + t];
    }
    __syncthreads();
    for (int i = t; i < KC * HF; i += blockDim.x) atomicAdd(&CFsum[i], acc[i]);
}

__global__ void k_ptab(const float* __restrict__ Wfc, const float* __restrict__ bfc,
                       const float* __restrict__ CFsum, const int* __restrict__ cnt,
                       float* __restrict__ PA, float* __restrict__ PB) {
    __shared__ float cf[HF];
    int k = blockIdx.y;
    int t = threadIdx.x;
    float cnv = (float)cnt[k];
    cf[t] = CFsum[k * HF + t] / cnv;
    __syncthreads();
    int o = blockIdx.x * 256 + t;
    const float* w = Wfc + (size_t)o * (2 * HF);
    float sa = 0.f, sb = 0.f;
#pragma unroll 4
    for (int j = 0; j < HF; j++) {
        float c = cf[j];
        sa = fmaf(c, w[j], sa);
        sb = fmaf(c, w[HF + j], sb);
    }
    float bb = bfc[o];
    PA[k * O2 + o] = sa + bb;
    PB[k * O2 + o] = sb + bb;
}

// ---------------- host launcher ---------------------------------------------
extern "C" void kernel_launch(void* const* d_in, const int* in_sizes, int n_in,
                              void* d_out, int out_size) {
    const float* x    = (const float*)d_in[0];
    const float* cid  = (const float*)d_in[1];
    const int*   cidx = (const int*)  d_in[2];
    const float* W1   = (const float*)d_in[3];
    const float* b1   = (const float*)d_in[4];
    const float* g1   = (const float*)d_in[5];
    const float* be1  = (const float*)d_in[6];
    const float* W2   = (const float*)d_in[7];
    const float* b2   = (const float*)d_in[8];
    const float* g2   = (const float*)d_in[9];
    const float* be2  = (const float*)d_in[10];
    const float* Wfc  = (const float*)d_in[11];
    const float* bfc  = (const float*)d_in[12];
    float* out = (float*)d_out;

    static bool inited = false;
    static float *H1, *H2, *XC, *sum1, *sq1, *a1, *c1, *sum2, *sq2, *a2, *c2,
                 *CFs, *PA, *PB;
    static int *cnt, *labs;
    static __nv_bfloat16 *xhi, *xlo, *W1h, *W1l, *A2h, *A2l, *W2h, *W2l,
                         *XCh, *XCl, *WCh, *WCl;
    if (!inited) {
        inited = true;
        cudaGetSymbolAddress((void**)&H1,   g_H1);
        cudaGetSymbolAddress((void**)&H2,   g_H2);
        cudaGetSymbolAddress((void**)&XC,   g_XC);
        cudaGetSymbolAddress((void**)&sum1, g_sum1);
        cudaGetSymbolAddress((void**)&sq1,  g_sq1);
        cudaGetSymbolAddress((void**)&a1,   g_a1);
        cudaGetSymbolAddress((void**)&c1,   g_c1);
        cudaGetSymbolAddress((void**)&sum2, g_sum2);
        cudaGetSymbolAddress((void**)&sq2,  g_sq2);
        cudaGetSymbolAddress((void**)&a2,   g_a2);
        cudaGetSymbolAddress((void**)&c2,   g_c2);
        cudaGetSymbolAddress((void**)&CFs,  g_CFsum);
        cudaGetSymbolAddress((void**)&PA,   g_PA);
        cudaGetSymbolAddress((void**)&PB,   g_PB);
        cudaGetSymbolAddress((void**)&cnt,  g_counts);
        cudaGetSymbolAddress((void**)&labs, g_labels);
        cudaGetSymbolAddress((void**)&xhi,  g_xhi);
        cudaGetSymbolAddress((void**)&xlo,  g_xlo);
        cudaGetSymbolAddress((void**)&W1h,  g_W1hi);
        cudaGetSymbolAddress((void**)&W1l,  g_W1lo);
        cudaGetSymbolAddress((void**)&A2h,  g_A2hi);
        cudaGetSymbolAddress((void**)&A2l,  g_A2lo);
        cudaGetSymbolAddress((void**)&W2h,  g_W2hi);
        cudaGetSymbolAddress((void**)&W2l,  g_W2lo);
        cudaGetSymbolAddress((void**)&XCh,  g_XChi);
        cudaGetSymbolAddress((void**)&XCl,  g_XClo);
        cudaGetSymbolAddress((void**)&WCh,  g_WChi);
        cudaGetSymbolAddress((void**)&WCl,  g_WClo);
        cudaFuncSetAttribute(k_bulkmma<0>,
                             cudaFuncAttributeMaxDynamicSharedMemorySize, SMEM_GG);
        cudaFuncSetAttribute(k_bulkmma<1>,
                             cudaFuncAttributeMaxDynamicSharedMemorySize, SMEM_GG);
    }

    // 0) zero accumulators
    k_zero<<<40, 256>>>(sum1, sq1, sum2, sq2, CFs, cnt);

    // splits of constant weights into tiled swizzled layout
    {
        long long t1 = (long long)HF * (KP1 / 8);
        k_split_t<<<cdiv_h((int)t1, 256), 256>>>(W1, W1h, W1l,
                                                 HF, D_IN, KP1 / 8, KP1 / 64, t1);
        long long t2 = (long long)HF * (HF / 8);
        k_split_t<<<cdiv_h((int)t2, 256), 256>>>(W2, W2h, W2l,
                                                 HF, HF, HF / 8, HF / 64, t2);
        k_split_wcat_t<<<cdiv_h(2048 * (HF / 8), 256), 256>>>(Wfc, WCh, WCl);
    }
    // split x (rows padded to NNP, K padded to 512)
    {
        long long t = (long long)NNP * (KP1 / 8);
        k_split_t<<<(int)((t + 255) / 256), 256>>>(x, xhi, xlo,
                                                   NN, D_IN, KP1 / 8, KP1 / 64, t);
    }

    // 1) H1 = x @ W1^T + b1
    {
        dim3 grid(HF / 128, NNP / 128);
        k_bulkmma<0><<<grid, 256, SMEM_GG>>>(xhi, xlo, W1h, W1l,
            NN, HF, KP1 / 64, b1, H1, nullptr, nullptr, nullptr, nullptr);
    }
    // 2) BN1 stats
    k_colstats<<<512, 256>>>(H1, sum1, sq1);
    k_finalize<<<1, 256>>>(sum1, sq1, g1, be1, a1, c1);

    // 3) A2 = relu(a1*H1 + c1) tiled split; H2 = A2 @ W2^T + b2
    {
        long long t = (long long)NNP * (HF / 8);
        k_split_aff_t<<<(int)((t + 255) / 256), 256>>>(H1, a1, c1, A2h, A2l, NN, t);
        dim3 grid(HF / 128, NNP / 128);
        k_bulkmma<0><<<grid, 256, SMEM_GG>>>(A2h, A2l, W2h, W2l,
            NN, HF, HF / 64, b2, H2, nullptr, nullptr, nullptr, nullptr);
    }
    // 4) BN2 stats
    k_colstats<<<512, 256>>>(H2, sum2, sq2);
    k_finalize<<<1, 256>>>(sum2, sq2, g2, be2, a2, c2);

    // 5) labels + counts
    k_labels<<<cdiv_h(MM, 256), 256>>>(cid, labs, cnt);

    // 6) XC = relu(a2 * H2[cidx] + c2): fp32 + fused tiled split
    k_make_xc<<<cdiv_h(MMP * (HF / 8), 256), 256>>>(H2, cidx, a2, c2, XC, XCh, XCl);

    // 7) cluster feature sums
    k_cluster_accum<<<256, 256>>>(XC, labs, CFs);

    // 8) PA/PB tables
    {
        dim3 grid(O2 / 256, KC);
        k_ptab<<<grid, 256>>>(Wfc, bfc, CFs, cnt, PA, PB);
    }

    // 9) final GEMM: Y = XC @ Wcat^T, epilogue adds PB/PA and scatters rows
    {
        dim3 grid(2048 / 128, MMP / 128);
        k_bulkmma<1><<<grid, 256, SMEM_GG>>>(XCh, XCl, WCh, WCl,
            MM, 2048, HF / 64, nullptr, nullptr, labs, PA, PB, out);
    }
}

// round 9
// speedup vs baseline: 2.3267x; 1.0041x over previous
#include <cuda_runtime.h>
#include <cuda_bf16.h>
#include <cstdint>

// ---------------- problem constants ----------------------------------------
#define NN   100000   // batch rows
#define NNP  100096   // padded to 128
#define D_IN 500      // input features
#define KP1  512      // D_IN padded to MMA K granularity
#define HF   256      // hidden
#define MM   50000    // cluster rows
#define MMP  50048    // padded to 128
#define KC   40       // clusters
#define O2   1024     // OUT*OUT
#define EPSV 1e-5f

static inline int cdiv_h(int a, int b) { return (a + b - 1) / b; }

// ---------------- device scratch --------------------------------------------
__device__ float g_H1[(size_t)NN * HF];
__device__ float g_H2[(size_t)NN * HF];
__device__ float g_XC[(size_t)MM * HF];
__device__ float g_sum1[HF], g_sq1[HF], g_a1[HF], g_c1[HF];
__device__ float g_sum2[HF], g_sq2[HF], g_a2[HF], g_c2[HF];
__device__ float g_CFsum[KC * HF];
__device__ int   g_counts[KC];
__device__ int   g_labels[MM];
__device__ float g_PA[KC * O2];
__device__ float g_PB[KC * O2];

// Pre-tiled, SW128-swizzled bf16 operands (hi + lo ~= fp32).
// Layout: tile (rowTile, kTile) of 128x64 bf16 = 16 KB contiguous at
// ((rowTile*KT + kTile) << 13) elements; inside, SW128 swizzle.
__device__ __nv_bfloat16 g_xhi[(size_t)NNP * KP1];
__device__ __nv_bfloat16 g_xlo[(size_t)NNP * KP1];
__device__ __nv_bfloat16 g_W1hi[(size_t)HF * KP1];
__device__ __nv_bfloat16 g_W1lo[(size_t)HF * KP1];
__device__ __nv_bfloat16 g_A2hi[(size_t)NNP * HF];
__device__ __nv_bfloat16 g_A2lo[(size_t)NNP * HF];
__device__ __nv_bfloat16 g_W2hi[(size_t)HF * HF];
__device__ __nv_bfloat16 g_W2lo[(size_t)HF * HF];
__device__ __nv_bfloat16 g_XChi[(size_t)MMP * HF];
__device__ __nv_bfloat16 g_XClo[(size_t)MMP * HF];
__device__ __nv_bfloat16 g_WChi[(size_t)2048 * HF];
__device__ __nv_bfloat16 g_WClo[(size_t)2048 * HF];

// ---------------- low-level helpers ------------------------------------------
__device__ __forceinline__ uint32_t smem_u32(const void* p) {
    uint32_t a;
    asm("{ .reg .u64 t; cvta.to.shared.u64 t, %1; cvt.u32.u64 %0, t; }"
        : "=r"(a) : "l"(p));
    return a;
}

// Bulk async copy: one instruction per 16 KB tile (UBLKCP) + mbarrier tx.
__device__ __forceinline__ void bulkcp(uint32_t dst, const void* src,
                                       uint32_t bytes, uint32_t mbar) {
    asm volatile(
        "cp.async.bulk.shared::cluster.global.mbarrier::complete_tx::bytes "
        "[%0], [%1], %2, [%3];"
        :: "r"(dst), "l"(src), "r"(bytes), "r"(mbar) : "memory");
}

#define MBAR_INIT(addr, cnt) \
    asm volatile("mbarrier.init.shared.b64 [%0], %1;" \
                 :: "r"((uint32_t)(addr)), "r"((uint32_t)(cnt)) : "memory")
#define MBAR_EXPECT(addr, tx) \
    asm volatile("mbarrier.arrive.expect_tx.shared.b64 _, [%0], %1;" \
                 :: "r"((uint32_t)(addr)), "r"((uint32_t)(tx)) : "memory")
#define MBAR_WAIT(addr, parity) do {                                           \
    uint32_t _m = (uint32_t)(addr); uint32_t _p = (uint32_t)(parity);          \
    uint32_t _d;                                                               \
    asm volatile("{\n\t.reg .pred p;\n\t"                                      \
        "mbarrier.try_wait.parity.acquire.cta.shared::cta.b64 p, [%1], %2;\n\t"\
        "selp.b32 %0, 1, 0, p;\n\t}" : "=r"(_d) : "r"(_m), "r"(_p) : "memory");\
    if (!_d) {                                                                 \
        asm volatile("{\n\t.reg .pred P1;\n\t"                                 \
            "WL_%=:\n\t"                                                       \
            "mbarrier.try_wait.parity.acquire.cta.shared::cta.b64 P1, [%0], %1, 0x989680;\n\t" \
            "@P1 bra.uni WD_%=;\n\t"                                           \
            "bra.uni WL_%=;\n\t"                                               \
            "WD_%=:\n\t}" :: "r"(_m), "r"(_p) : "memory");                     \
    }                                                                          \
} while (0)

__device__ __forceinline__ void ldsm4(uint32_t* r, uint32_t addr) {
    asm volatile("ldmatrix.sync.aligned.m8n8.x4.shared.b16 {%0,%1,%2,%3}, [%4];"
                 : "=r"(r[0]), "=r"(r[1]), "=r"(r[2]), "=r"(r[3]) : "r"(addr));
}

__device__ __forceinline__ void mma16816(float* d, const uint32_t* a,
                                         uint32_t b0, uint32_t b1) {
    asm volatile(
        "mma.sync.aligned.m16n8k16.row.col.f32.bf16.bf16.f32 "
        "{%0,%1,%2,%3}, {%4,%5,%6,%7}, {%8,%9}, {%0,%1,%2,%3};"
        : "+f"(d[0]), "+f"(d[1]), "+f"(d[2]), "+f"(d[3])
        : "r"(a[0]), "r"(a[1]), "r"(a[2]), "r"(a[3]), "r"(b0), "r"(b1));
}

// Element offset inside the tiled+swizzled operand layout.
__device__ __forceinline__ size_t tileoff(int row, int k, int KT) {
    size_t base = ((size_t)((row >> 7) * KT + (k >> 6))) << 13;
    uint32_t boff = ((uint32_t)(row & 127) << 7) | ((uint32_t)(k & 63) << 1);
    uint32_t sw = boff ^ ((boff >> 3) & 0x70);
    return base + (sw >> 1);
}

__device__ __forceinline__ uint32_t swz(uint32_t boff) {
    return boff ^ ((boff >> 3) & 0x70);
}

// ---------------- bulk-loaded tensor-core GEMM ------------------------------
// C[MrowsTrue, Ncols] = (Ahi+Alo)[.,K] @ (Bhi+Blo)[Ncols,K]^T  (split-bf16,
// lo*lo dropped).  Operands pre-tiled 128x64 SW128 blocks.
// MODE 0: C[r*Ncols + c] = acc + bias[c]
// MODE 1: layer-3 epilogue: +PB/PA[label] table, 2M-row output layout
#define TILE16K 16384
#define STG64K  65536
#define NSTAGE  3
#define SMEM_GG (NSTAGE * STG64K + 32)   // + mbarriers

template <int MODE>
__global__ void __launch_bounds__(256)
k_bulkmma(const __nv_bfloat16* __restrict__ Ahi, const __nv_bfloat16* __restrict__ Alo,
          const __nv_bfloat16* __restrict__ Bhi, const __nv_bfloat16* __restrict__ Blo,
          int Mrows, int Ncols, int KT,
          const float* __restrict__ bias, float* __restrict__ Cmat,
          const int* __restrict__ labels, const float* __restrict__ PA,
          const float* __restrict__ PB, float* __restrict__ out) {
    extern __shared__ unsigned char smem[];
    const uint32_t sb = smem_u32(smem);
    const uint32_t mb = sb + NSTAGE * STG64K;   // 3 mbarriers, 8 B apart
    const int tx = threadIdx.x;
    const int lane = tx & 31, wid = tx >> 5;
    const int warpM = wid & 3;           // 4 warps over M (32 rows each)
    const int warpN = wid >> 2;          // 2 warps over N (64 cols each)
    const int rowBase = blockIdx.y * 128;
    const int colBase = blockIdx.x * 128;

    if (tx == 0) {
        MBAR_INIT(mb + 0, 1);
        MBAR_INIT(mb + 8, 1);
        MBAR_INIT(mb + 16, 1);
    }
    __syncthreads();

    const size_t aBase = ((size_t)blockIdx.y * KT) << 13;
    const size_t bBase = ((size_t)blockIdx.x * KT) << 13;

    // prologue: issue up to 3 chunks
    if (tx == 0) {
        const int pre = (KT < NSTAGE) ? KT : NSTAGE;
        for (int s = 0; s < pre; s++) {
            const size_t off = aBase + ((size_t)s << 13);
            const size_t bof = bBase + ((size_t)s << 13);
            MBAR_EXPECT(mb + 8 * s, STG64K);
            uint32_t d = sb + (uint32_t)s * STG64K;
            bulkcp(d + 0 * TILE16K, Ahi + off, TILE16K, mb + 8 * s);
            bulkcp(d + 1 * TILE16K, Alo + off, TILE16K, mb + 8 * s);
            bulkcp(d + 2 * TILE16K, Bhi + bof, TILE16K, mb + 8 * s);
            bulkcp(d + 3 * TILE16K, Blo + bof, TILE16K, mb + 8 * s);
        }
    }

    float acc[2][8][4];
#pragma unroll
    for (int i = 0; i < 2; i++)
#pragma unroll
        for (int j = 0; j < 8; j++)
#pragma unroll
            for (int q = 0; q < 4; q++) acc[i][j][q] = 0.f;

    int ph[NSTAGE] = {0, 0, 0};
    for (int c = 0; c < KT; c++) {
        const int s = c % NSTAGE;
        MBAR_WAIT(mb + 8 * s, ph[s]);
        ph[s] ^= 1;
        const uint32_t stg = sb + (uint32_t)s * STG64K;
#pragma unroll
        for (int ks = 0; ks < 4; ks++) {
            const int k0 = ks * 16;
            // ---- load ALL fragments for this k-step first ----
            uint32_t ah[2][4], al[2][4], bh[4][4], bl[4][4];
#pragma unroll
            for (int mf = 0; mf < 2; mf++) {
                uint32_t boff = ((uint32_t)(warpM * 32 + mf * 16 + (lane & 15)) << 7) |
                                ((uint32_t)(k0 + (lane >> 4) * 8) << 1);
                uint32_t off = swz(boff);
                ldsm4(ah[mf], stg + 0 * TILE16K + off);
                ldsm4(al[mf], stg + 1 * TILE16K + off);
            }
            {
                const int grp = lane >> 3, rin = lane & 7;
#pragma unroll
                for (int p = 0; p < 4; p++) {
                    uint32_t boff = ((uint32_t)(warpN * 64 + p * 16 + (grp >> 1) * 8 + rin) << 7) |
                                    ((uint32_t)(k0 + (grp & 1) * 8) << 1);
                    uint32_t off = swz(boff);
                    ldsm4(bh[p], stg + 2 * TILE16K + off);
                    ldsm4(bl[p], stg + 3 * TILE16K + off);
                }
            }
            // ---- term-major MMA issue: 16 independent accs between reuses ----
            // term 1: hi * hi
#pragma unroll
            for (int p = 0; p < 4; p++)
#pragma unroll
                for (int mf = 0; mf < 2; mf++) {
                    mma16816(acc[mf][2 * p + 0], ah[mf], bh[p][0], bh[p][1]);
                    mma16816(acc[mf][2 * p + 1], ah[mf], bh[p][2], bh[p][3]);
                }
            // term 2: hi * lo
#pragma unroll
            for (int p = 0; p < 4; p++)
#pragma unroll
                for (int mf = 0; mf < 2; mf++) {
                    mma16816(acc[mf][2 * p + 0], ah[mf], bl[p][0], bl[p][1]);
                    mma16816(acc[mf][2 * p + 1], ah[mf], bl[p][2], bl[p][3]);
                }
            // term 3: lo * hi
#pragma unroll
            for (int p = 0; p < 4; p++)
#pragma unroll
                for (int mf = 0; mf < 2; mf++) {
                    mma16816(acc[mf][2 * p + 0], al[mf], bh[p][0], bh[p][1]);
                    mma16816(acc[mf][2 * p + 1], al[mf], bh[p][2], bh[p][3]);
                }
        }
        __syncthreads();   // all warps done with stage s before refill
        if (c + NSTAGE < KT && tx == 0) {
            const int cn = c + NSTAGE;
            const size_t off = aBase + ((size_t)cn << 13);
            const size_t bof = bBase + ((size_t)cn << 13);
            MBAR_EXPECT(mb + 8 * s, STG64K);
            uint32_t d = sb + (uint32_t)s * STG64K;
            bulkcp(d + 0 * TILE16K, Ahi + off, TILE16K, mb + 8 * s);
            bulkcp(d + 1 * TILE16K, Alo + off, TILE16K, mb + 8 * s);
            bulkcp(d + 2 * TILE16K, Bhi + bof, TILE16K, mb + 8 * s);
            bulkcp(d + 3 * TILE16K, Blo + bof, TILE16K, mb + 8 * s);
        }
    }

    // ---------------- epilogue (same fragment layout as R7, proven) ----------
#pragma unroll
    for (int mf = 0; mf < 2; mf++) {
#pragma unroll
        for (int half = 0; half < 2; half++) {
            const int r = rowBase + warpM * 32 + mf * 16 + (lane >> 2) + half * 8;
            if (r >= Mrows) continue;
            if (MODE == 0) {
                float* cp = Cmat + (size_t)r * Ncols;
#pragma unroll
                for (int nf = 0; nf < 8; nf++) {
                    const int cc = colBase + warpN * 64 + nf * 8 + (lane & 3) * 2;
                    float2 b = *(const float2*)(bias + cc);
                    float2 v;
                    v.x = acc[mf][nf][half * 2 + 0] + b.x;
                    v.y = acc[mf][nf][half * 2 + 1] + b.y;
                    *(float2*)(cp + cc) = v;
                }
            } else {
                const bool hB = colBase >= 1024;   // Wcat rows >=1024 = WfcB half
                const int lab = labels[r];
                const float* P = hB ? PA : PB;
                const float* pl = P + (size_t)lab * O2;
                float* op = out + ((size_t)r + (hB ? (size_t)MM : 0)) * O2;
                const int cB = (colBase & 1023) + warpN * 64;
#pragma unroll
                for (int nf = 0; nf < 8; nf++) {
                    const int col = cB + nf * 8 + (lane & 3) * 2;
                    float2 p = *(const float2*)(pl + col);
                    float2 v;
                    v.x = acc[mf][nf][half * 2 + 0] + p.x;
                    v.y = acc[mf][nf][half * 2 + 1] + p.y;
                    *(float2*)(op + col) = v;
                }
            }
        }
    }
}

// ---------------- split kernels: fp32 -> tiled swizzled bf16 hi/lo ----------
// One thread handles 8 consecutive k (one 16-B swizzled group).
__global__ void k_split_t(const float* __restrict__ src,
                          __nv_bfloat16* __restrict__ hi,
                          __nv_bfloat16* __restrict__ lo,
                          int rowsSrc, int colsSrc, int K8, int KT,
                          long long total) {
    long long idx = blockIdx.x * (long long)blockDim.x + threadIdx.x;
    if (idx >= total) return;
    int row = (int)(idx / K8);
    int k   = (int)(idx % K8) * 8;
    __nv_bfloat16 h8[8], l8[8];
#pragma unroll
    for (int j = 0; j < 8; j++) {
        float v = 0.f;
        if (row < rowsSrc && k + j < colsSrc)
            v = src[(size_t)row * colsSrc + k + j];
        __nv_bfloat16 h = __float2bfloat16(v);
        h8[j] = h;
        l8[j] = __float2bfloat16(v - __bfloat162float(h));
    }
    size_t off = tileoff(row, k, KT);
    *(uint4*)(hi + off) = *(uint4*)h8;
    *(uint4*)(lo + off) = *(uint4*)l8;
}

__global__ void k_split_aff_t(const float* __restrict__ src,
                              const float* __restrict__ aa, const float* __restrict__ cc,
                              __nv_bfloat16* __restrict__ hi,
                              __nv_bfloat16* __restrict__ lo,
                              int rowsSrc, long long total) {
    long long idx = blockIdx.x * (long long)blockDim.x + threadIdx.x;
    if (idx >= total) return;
    int row = (int)(idx / (HF / 8));
    int k   = (int)(idx % (HF / 8)) * 8;
    __nv_bfloat16 h8[8], l8[8];
#pragma unroll
    for (int j = 0; j < 8; j++) {
        float v = 0.f;
        if (row < rowsSrc) {
            v = fmaxf(fmaf(aa[k + j], src[(size_t)row * HF + k + j], cc[k + j]), 0.f);
        }
        __nv_bfloat16 h = __float2bfloat16(v);
        h8[j] = h;
        l8[j] = __float2bfloat16(v - __bfloat162float(h));
    }
    size_t off = tileoff(row, k, HF / 64);
    *(uint4*)(hi + off) = *(uint4*)h8;
    *(uint4*)(lo + off) = *(uint4*)l8;
}

// Wcat[2048,256]: rows 0..1023 = Wfc[:, :256]; rows 1024..2047 = Wfc[:, 256:]
__global__ void k_split_wcat_t(const float* __restrict__ Wfc,
                               __nv_bfloat16* __restrict__ hi,
                               __nv_bfloat16* __restrict__ lo) {
    int idx = blockIdx.x * blockDim.x + threadIdx.x;   // 2048 * 32 groups
    if (idx >= 2048 * (HF / 8)) return;
    int o = idx / (HF / 8);
    int k = (idx % (HF / 8)) * 8;
    const float* w = (o < 1024) ? (Wfc + (size_t)o * (2 * HF))
                                : (Wfc + (size_t)(o - 1024) * (2 * HF) + HF);
    __nv_bfloat16 h8[8], l8[8];
#pragma unroll
    for (int j = 0; j < 8; j++) {
        float v = w[k + j];
        __nv_bfloat16 h = __float2bfloat16(v);
        h8[j] = h;
        l8[j] = __float2bfloat16(v - __bfloat162float(h));
    }
    size_t off = tileoff(o, k, HF / 64);
    *(uint4*)(hi + off) = *(uint4*)h8;
    *(uint4*)(lo + off) = *(uint4*)l8;
}

// ---------------- stats / labels / segment mean (unchanged, proven) ---------
__global__ void k_zero(float* s1, float* q1, float* s2, float* q2,
                       float* cfs, int* cnt) {
    int t = blockIdx.x * blockDim.x + threadIdx.x;
    if (t < HF) { s1[t] = 0.f; q1[t] = 0.f; s2[t] = 0.f; q2[t] = 0.f; }
    if (t < KC) cnt[t] = 0;
    if (t < KC * HF) cfs[t] = 0.f;
}

__global__ void k_colstats(const float* __restrict__ H,
                           float* __restrict__ sum, float* __restrict__ sq) {
    int t = threadIdx.x;
    int per = (NN + gridDim.x - 1) / gridDim.x;
    int r0 = blockIdx.x * per;
    int r1 = min(NN, r0 + per);
    float s = 0.f, q = 0.f;
    for (int r = r0; r < r1; r++) {
        float v = H[(size_t)r * HF + t];
        s += v;
        q = fmaf(v, v, q);
    }
    atomicAdd(&sum[t], s);
    atomicAdd(&sq[t], q);
}

__global__ void k_finalize(const float* __restrict__ sum, const float* __restrict__ sq,
                           const float* __restrict__ gam, const float* __restrict__ bet,
                           float* __restrict__ a, float* __restrict__ c) {
    int t = threadIdx.x;
    const float invN = 1.0f / (float)NN;
    float mean = sum[t] * invN;
    float var  = sq[t] * invN - mean * mean;
    float inv  = rsqrtf(var + EPSV);
    float aa   = gam[t] * inv;
    a[t] = aa;
    c[t] = bet[t] - mean * aa;
}

__global__ void k_labels(const float* __restrict__ cid,
                         int* __restrict__ labels, int* __restrict__ cnt) {
    int m = blockIdx.x * blockDim.x + threadIdx.x;
    if (m >= MM) return;
    const float* row = cid + (size_t)m * KC;
    int best = 0;
    float bv = row[0];
#pragma unroll
    for (int k = 1; k < KC; k++) {
        float v = row[k];
        if (v > bv) { bv = v; best = k; }
    }
    labels[m] = best;
    atomicAdd(&cnt[best], 1);
}

// XC = relu(a2*H2[ci[m]] + c2): fp32 copy (for cluster sums) + tiled split
__global__ void k_make_xc(const float* __restrict__ H2, const int* __restrict__ ci,
                          const float* __restrict__ a2, const float* __restrict__ c2,
                          float* __restrict__ XC,
                          __nv_bfloat16* __restrict__ hi,
                          __nv_bfloat16* __restrict__ lo) {
    int idx = blockIdx.x * blockDim.x + threadIdx.x;   // MMP * 32 groups of 8
    if (idx >= MMP * (HF / 8)) return;
    int m = idx / (HF / 8);
    int k = (idx % (HF / 8)) * 8;
    __nv_bfloat16 h8[8], l8[8];
    float o8[8];
#pragma unroll
    for (int j = 0; j < 8; j++) o8[j] = 0.f;
    if (m < MM) {
        int r = ci[m];
        const float* hp = H2 + (size_t)r * HF + k;
#pragma unroll
        for (int j = 0; j < 8; j++)
            o8[j] = fmaxf(fmaf(a2[k + j], hp[j], c2[k + j]), 0.f);
        float4* xp = (float4*)(XC + (size_t)m * HF + k);
        xp[0] = make_float4(o8[0], o8[1], o8[2], o8[3]);
        xp[1] = make_float4(o8[4], o8[5], o8[6], o8[7]);
    }
#pragma unroll
    for (int j = 0; j < 8; j++) {
        __nv_bfloat16 h = __float2bfloat16(o8[j]);
        h8[j] = h;
        l8[j] = __float2bfloat16(o8[j] - __bfloat162float(h));
    }
    size_t off = tileoff(m, k, HF / 64);
    *(uint4*)(hi + off) = *(uint4*)h8;
    *(uint4*)(lo + off) = *(uint4*)l8;
}

__global__ void k_cluster_accum(const float* __restrict__ XC,
                                const int* __restrict__ labels,
                                float* __restrict__ CFsum) {
    __shared__ float acc[KC * HF];
    int t = threadIdx.x;
    for (int i = t; i < KC * HF; i += blockDim.x) acc[i] = 0.f;
    __syncthreads();
    int per = (MM + gridDim.x - 1) / gridDim.x;
    int m0 = blockIdx.x * per;
    int m1 = min(MM, m0 + per);
    for (int m = m0; m < m1; m++) {
        int lab = labels[m];
        acc[lab * HF + t] += XC[(size_t)m * HF + t];
    }
    __syncthreads();
    for (int i = t; i < KC * HF; i += blockDim.x) atomicAdd(&CFsum[i], acc[i]);
}

__global__ void k_ptab(const float* __restrict__ Wfc, const float* __restrict__ bfc,
                       const float* __restrict__ CFsum, const int* __restrict__ cnt,
                       float* __restrict__ PA, float* __restrict__ PB) {
    __shared__ float cf[HF];
    int k = blockIdx.y;
    int t = threadIdx.x;
    float cnv = (float)cnt[k];
    cf[t] = CFsum[k * HF + t] / cnv;
    __syncthreads();
    int o = blockIdx.x * 256 + t;
    const float* w = Wfc + (size_t)o * (2 * HF);
    float sa = 0.f, sb = 0.f;
#pragma unroll 4
    for (int j = 0; j < HF; j++) {
        float c = cf[j];
        sa = fmaf(c, w[j], sa);
        sb = fmaf(c, w[HF + j], sb);
    }
    float bb = bfc[o];
    PA[k * O2 + o] = sa + bb;
    PB[k * O2 + o] = sb + bb;
}

// ---------------- host launcher ---------------------------------------------
extern "C" void kernel_launch(void* const* d_in, const int* in_sizes, int n_in,
                              void* d_out, int out_size) {
    const float* x    = (const float*)d_in[0];
    const float* cid  = (const float*)d_in[1];
    const int*   cidx = (const int*)  d_in[2];
    const float* W1   = (const float*)d_in[3];
    const float* b1   = (const float*)d_in[4];
    const float* g1   = (const float*)d_in[5];
    const float* be1  = (const float*)d_in[6];
    const float* W2   = (const float*)d_in[7];
    const float* b2   = (const float*)d_in[8];
    const float* g2   = (const float*)d_in[9];
    const float* be2  = (const float*)d_in[10];
    const float* Wfc  = (const float*)d_in[11];
    const float* bfc  = (const float*)d_in[12];
    float* out = (float*)d_out;

    static bool inited = false;
    static float *H1, *H2, *XC, *sum1, *sq1, *a1, *c1, *sum2, *sq2, *a2, *c2,
                 *CFs, *PA, *PB;
    static int *cnt, *labs;
    static __nv_bfloat16 *xhi, *xlo, *W1h, *W1l, *A2h, *A2l, *W2h, *W2l,
                         *XCh, *XCl, *WCh, *WCl;
    if (!inited) {
        inited = true;
        cudaGetSymbolAddress((void**)&H1,   g_H1);
        cudaGetSymbolAddress((void**)&H2,   g_H2);
        cudaGetSymbolAddress((void**)&XC,   g_XC);
        cudaGetSymbolAddress((void**)&sum1, g_sum1);
        cudaGetSymbolAddress((void**)&sq1,  g_sq1);
        cudaGetSymbolAddress((void**)&a1,   g_a1);
        cudaGetSymbolAddress((void**)&c1,   g_c1);
        cudaGetSymbolAddress((void**)&sum2, g_sum2);
        cudaGetSymbolAddress((void**)&sq2,  g_sq2);
        cudaGetSymbolAddress((void**)&a2,   g_a2);
        cudaGetSymbolAddress((void**)&c2,   g_c2);
        cudaGetSymbolAddress((void**)&CFs,  g_CFsum);
        cudaGetSymbolAddress((void**)&PA,   g_PA);
        cudaGetSymbolAddress((void**)&PB,   g_PB);
        cudaGetSymbolAddress((void**)&cnt,  g_counts);
        cudaGetSymbolAddress((void**)&labs, g_labels);
        cudaGetSymbolAddress((void**)&xhi,  g_xhi);
        cudaGetSymbolAddress((void**)&xlo,  g_xlo);
        cudaGetSymbolAddress((void**)&W1h,  g_W1hi);
        cudaGetSymbolAddress((void**)&W1l,  g_W1lo);
        cudaGetSymbolAddress((void**)&A2h,  g_A2hi);
        cudaGetSymbolAddress((void**)&A2l,  g_A2lo);
        cudaGetSymbolAddress((void**)&W2h,  g_W2hi);
        cudaGetSymbolAddress((void**)&W2l,  g_W2lo);
        cudaGetSymbolAddress((void**)&XCh,  g_XChi);
        cudaGetSymbolAddress((void**)&XCl,  g_XClo);
        cudaGetSymbolAddress((void**)&WCh,  g_WChi);
        cudaGetSymbolAddress((void**)&WCl,  g_WClo);
        cudaFuncSetAttribute(k_bulkmma<0>,
                             cudaFuncAttributeMaxDynamicSharedMemorySize, SMEM_GG);
        cudaFuncSetAttribute(k_bulkmma<1>,
                             cudaFuncAttributeMaxDynamicSharedMemorySize, SMEM_GG);
    }

    // 0) zero accumulators
    k_zero<<<40, 256>>>(sum1, sq1, sum2, sq2, CFs, cnt);

    // splits of constant weights into tiled swizzled layout
    {
        long long t1 = (long long)HF * (KP1 / 8);
        k_split_t<<<cdiv_h((int)t1, 256), 256>>>(W1, W1h, W1l,
                                                 HF, D_IN, KP1 / 8, KP1 / 64, t1);
        long long t2 = (long long)HF * (HF / 8);
        k_split_t<<<cdiv_h((int)t2, 256), 256>>>(W2, W2h, W2l,
                                                 HF, HF, HF / 8, HF / 64, t2);
        k_split_wcat_t<<<cdiv_h(2048 * (HF / 8), 256), 256>>>(Wfc, WCh, WCl);
    }
    // split x (rows padded to NNP, K padded to 512)
    {
        long long t = (long long)NNP * (KP1 / 8);
        k_split_t<<<(int)((t + 255) / 256), 256>>>(x, xhi, xlo,
                                                   NN, D_IN, KP1 / 8, KP1 / 64, t);
    }

    // 1) H1 = x @ W1^T + b1
    {
        dim3 grid(HF / 128, NNP / 128);
        k_bulkmma<0><<<grid, 256, SMEM_GG>>>(xhi, xlo, W1h, W1l,
            NN, HF, KP1 / 64, b1, H1, nullptr, nullptr, nullptr, nullptr);
    }
    // 2) BN1 stats
    k_colstats<<<512, 256>>>(H1, sum1, sq1);
    k_finalize<<<1, 256>>>(sum1, sq1, g1, be1, a1, c1);

    // 3) A2 = relu(a1*H1 + c1) tiled split; H2 = A2 @ W2^T + b2
    {
        long long t = (long long)NNP * (HF / 8);
        k_split_aff_t<<<(int)((t + 255) / 256), 256>>>(H1, a1, c1, A2h, A2l, NN, t);
        dim3 grid(HF / 128, NNP / 128);
        k_bulkmma<0><<<grid, 256, SMEM_GG>>>(A2h, A2l, W2h, W2l,
            NN, HF, HF / 64, b2, H2, nullptr, nullptr, nullptr, nullptr);
    }
    // 4) BN2 stats
    k_colstats<<<512, 256>>>(H2, sum2, sq2);
    k_finalize<<<1, 256>>>(sum2, sq2, g2, be2, a2, c2);

    // 5) labels + counts
    k_labels<<<cdiv_h(MM, 256), 256>>>(cid, labs, cnt);

    // 6) XC = relu(a2 * H2[cidx] + c2): fp32 + fused tiled split
    k_make_xc<<<cdiv_h(MMP * (HF / 8), 256), 256>>>(H2, cidx, a2, c2, XC, XCh, XCl);

    // 7) cluster feature sums
    k_cluster_accum<<<256, 256>>>(XC, labs, CFs);

    // 8) PA/PB tables
    {
        dim3 grid(O2 / 256, KC);
        k_ptab<<<grid, 256>>>(Wfc, bfc, CFs, cnt, PA, PB);
    }

    // 9) final GEMM: Y = XC @ Wcat^T, epilogue adds PB/PA and scatters rows
    {
        dim3 grid(2048 / 128, MMP / 128);
        k_bulkmma<1><<<grid, 256, SMEM_GG>>>(XCh, XCl, WCh, WCl,
            MM, 2048, HF / 64, nullptr, nullptr, labs, PA, PB, out);
    }
}